// round 13
// baseline (speedup 1.0000x reference)
#include <cuda_runtime.h>
#include <cstdint>

// ---------------------------------------------------------------------------
// SimpleModalityUntiedAttention: B=2 S=2048 D=1024 H=16 HD=64 M=2 E=1024
// Round 13: 3-stage cp.async pipelines (wait_group 1) in k_qkv / k_oproj.
// flash/attnw identical to R12 (static-bound softmax).
// ---------------------------------------------------------------------------

namespace {
constexpr int kB  = 2;
constexpr int kS  = 2048;
constexpr int kD  = 1024;
constexpr int kH  = 16;
constexpr int kHD = 64;
constexpr int kM  = 2;
constexpr int kE  = 1024;
constexpr int kNR = kB * kS;
constexpr float kEps   = 1e-5f;
constexpr float kScale = 0.125f;
constexpr float kL2E   = 1.44269504088896340736f;
}

__device__ float g_q[kNR * kE];
__device__ float g_k[kNR * kE];
__device__ float g_v[kNR * kE];
__device__ float g_ctx[kNR * kE];
__device__ float g_o[kNR * kD];
__device__ float g_ml[kB * kH * kS * 2];   // (B2 log2 units, sumexp)
__device__ float g_mrow2[kS];
__device__ int   g_idx[kM * kNR];
__device__ int   g_cnt[kM];
__device__ float g_xr[kNR * kD];
__device__ float g_wq[kM * kD * kE];
__device__ float g_wk[kM * kD * kE];
__device__ float g_wv[kM * kD * kE];
__device__ float g_wo[kM * kE * kD];

__device__ __forceinline__ float f2tf(float x) {
    uint32_t u;
    asm("cvt.rna.tf32.f32 %0, %1;" : "=r"(u) : "f"(x));
    return __uint_as_float(u);
}
__device__ __forceinline__ uint32_t fu(float x) { return __float_as_uint(x); }
__device__ __forceinline__ float ex2(float x) {
    float r;
    asm("ex2.approx.f32 %0, %1;" : "=f"(r) : "f"(x));
    return r;
}

__device__ __forceinline__ void mma_tf32(float* d, const uint32_t* a, const uint32_t* b) {
    asm volatile(
        "mma.sync.aligned.m16n8k8.row.col.f32.tf32.tf32.f32 "
        "{%0,%1,%2,%3}, {%4,%5,%6,%7}, {%8,%9}, {%0,%1,%2,%3};"
        : "+f"(d[0]), "+f"(d[1]), "+f"(d[2]), "+f"(d[3])
        : "r"(a[0]), "r"(a[1]), "r"(a[2]), "r"(a[3]), "r"(b[0]), "r"(b[1]));
}

__device__ __forceinline__ void ldsm4(uint32_t* r, uint32_t saddr) {
    asm volatile("ldmatrix.sync.aligned.m8n8.x4.shared.b16 {%0,%1,%2,%3}, [%4];"
        : "=r"(r[0]), "=r"(r[1]), "=r"(r[2]), "=r"(r[3]) : "r"(saddr));
}
__device__ __forceinline__ uint32_t sptr(const void* p) {
    return (uint32_t)__cvta_generic_to_shared(p);
}

__device__ __forceinline__ void cpa16(void* dst_smem, const void* src) {
    uint32_t d = (uint32_t)__cvta_generic_to_shared(dst_smem);
    asm volatile("cp.async.cg.shared.global [%0], [%1], 16;" :: "r"(d), "l"(src));
}
#define CPA_COMMIT() asm volatile("cp.async.commit_group;")
#define CPA_WAIT(N)  asm volatile("cp.async.wait_group %0;" :: "n"(N))

// ---------------------------------------------------------------------------
// K-1: merged tf32 round-copy of x + 4 weight tensors
// ---------------------------------------------------------------------------
__global__ __launch_bounds__(256) void k_round_all(
    const float* __restrict__ x,
    const float* __restrict__ Wq, const float* __restrict__ Wk,
    const float* __restrict__ Wv, const float* __restrict__ Wo)
{
    constexpr int NX4 = kNR * kD / 4;
    constexpr int NW4 = kM * kD * kE / 4;
    int i = blockIdx.x * 256 + threadIdx.x;
    const float* src;
    float* dst;
    int off;
    if (i < NX4) {
        src = x; dst = g_xr; off = i;
    } else {
        int j = i - NX4;
        int t = j >> 19;
        off = j & (NW4 - 1);
        src = (t == 0) ? Wq : (t == 1) ? Wk : (t == 2) ? Wv : Wo;
        dst = (t == 0) ? g_wq : (t == 1) ? g_wk : (t == 2) ? g_wv : g_wo;
    }
    float4 v = ((const float4*)src)[off];
    float4 r = {f2tf(v.x), f2tf(v.y), f2tf(v.z), f2tf(v.w)};
    ((float4*)dst)[off] = r;
}

// ---------------------------------------------------------------------------
// K-2: per-row mask max -> static softmax bound B2(q)
// ---------------------------------------------------------------------------
__global__ __launch_bounds__(256) void k_mrow(const float* __restrict__ mask)
{
    const int q = blockIdx.x;
    const int tid = threadIdx.x;
    float m = -3e38f;
    const float* row = mask + (size_t)q * kS;
    for (int k = tid; k < kS; k += 256) m = fmaxf(m, row[k]);
#pragma unroll
    for (int off = 16; off > 0; off >>= 1)
        m = fmaxf(m, __shfl_xor_sync(0xffffffffu, m, off));
    __shared__ float red[8];
    if ((tid & 31) == 0) red[tid >> 5] = m;
    __syncthreads();
    if (tid == 0) {
        float t = red[0];
#pragma unroll
        for (int w = 1; w < 8; ++w) t = fmaxf(t, red[w]);
        g_mrow2[q] = (8.25f + t) * kL2E;
    }
}

// ---------------------------------------------------------------------------
// K0: modality compaction
// ---------------------------------------------------------------------------
__global__ __launch_bounds__(1024) void k_compact(const int* __restrict__ mod_ids)
{
    __shared__ int cnt[kM];
    const int tid = threadIdx.x;
    if (tid < kM) cnt[tid] = 0;
    __syncthreads();
    for (int r = tid; r < kNR; r += 1024) {
        int m = mod_ids[r];
        int pos = atomicAdd(&cnt[m], 1);
        g_idx[m * kNR + pos] = r;
    }
    __syncthreads();
    int c0 = cnt[0], c1 = cnt[1];
    if (tid == 0) { g_cnt[0] = c0; g_cnt[1] = c1; }
    for (int i = c0 + tid; i < kNR; i += 1024) g_idx[i] = 0;
    for (int i = c1 + tid; i < kNR; i += 1024) g_idx[kNR + i] = 0;
}

// ---------------------------------------------------------------------------
// 3-stage GEMM smem layout (floats): As[st] at st*4608 (st=0..2),
// Bs[st] at 13824 + st*4352. Total 26880 fl = 107520 B.
// ---------------------------------------------------------------------------

// ---------------------------------------------------------------------------
// K1: QKV projection, 3-stage cp.async pipeline (wait_group 1)
// ---------------------------------------------------------------------------
__global__ __launch_bounds__(256) void k_qkv(
    const float* __restrict__ qn_w, const float* __restrict__ kn_w)
{
    extern __shared__ float sh[];
    const int z = blockIdx.z;
    const int m = z / 3;
    const int which = z % 3;
    const int cnt = g_cnt[m];
    const int rows = blockIdx.y * 128;
    if (rows >= cnt) return;

    const float* W = ((which == 0) ? g_wq : (which == 1) ? g_wk : g_wv)
                     + (size_t)m * kD * kE;
    float* Cout = (which == 0) ? g_q : (which == 1) ? g_k : g_v;
    const int* idx = g_idx + m * kNR;

    const int tid = threadIdx.x;
    const int wid = tid >> 5, lane = tid & 31;
    const int lg = lane >> 2, lt = lane & 3;
    const int mj = lane >> 3, mi2 = lane & 7;
    const int wm = wid & 3, wn = wid >> 2;
    const int cols = blockIdx.x * 128;

    float d[2][8][4] = {};

    const int arow = tid >> 3;
    const int ac4  = (tid & 7) << 2;
    const float* aptr[4];
#pragma unroll
    for (int i = 0; i < 4; ++i)
        aptr[i] = g_xr + (size_t)idx[rows + arow + 32 * i] * kD + ac4;
    const int brow = tid >> 5;
    const int bc4  = (tid & 31) << 2;
    const float* bptr = W + (size_t)brow * kE + cols + bc4;

    uint32_t aabase[3];
#pragma unroll
    for (int st = 0; st < 3; ++st)
        aabase[st] = sptr(sh + st * 4608 +
                          (wm * 32 + ((mj & 1) << 3) + mi2) * 36 + ((mj >> 1) << 2));

    auto issue = [&](int st, int k0) {
        float* as = sh + st * 4608;
        float* bs = sh + 13824 + st * 4352;
#pragma unroll
        for (int i = 0; i < 4; ++i)
            cpa16(as + (arow + 32 * i) * 36 + ac4, aptr[i] + k0);
#pragma unroll
        for (int i = 0; i < 4; ++i)
            cpa16(bs + (brow + 8 * i) * 136 + bc4, bptr + (size_t)(k0 + 8 * i) * kE);
    };

    issue(0, 0);  CPA_COMMIT();
    issue(1, 32); CPA_COMMIT();

    constexpr int NIT = kD / 32;
    int st = 0;
    for (int kb = 0; kb < NIT; ++kb) {
        CPA_WAIT(1);          // stage kb complete (kb+1 may be in flight)
        __syncthreads();
        if (kb + 2 < NIT) {   // refill stage (kb-1)'s buffer = (st+2)%3
            int nst = (st + 2 >= 3) ? st - 1 : st + 2;
            issue(nst, (kb + 2) * 32);
            CPA_COMMIT();
        }

        const float* bs = sh + 13824 + st * 4352;
#pragma unroll
        for (int ks = 0; ks < 32; ks += 8) {
            uint32_t a[2][4], b[8][2];
            ldsm4(a[0], aabase[st] + ks * 4);
            ldsm4(a[1], aabase[st] + 2304 + ks * 4);
#pragma unroll
            for (int ni = 0; ni < 8; ++ni) {
                int n = wn * 64 + ni * 8 + lg;
                b[ni][0] = fu(bs[(ks + lt) * 136 + n]);
                b[ni][1] = fu(bs[(ks + 4 + lt) * 136 + n]);
            }
#pragma unroll
            for (int mi = 0; mi < 2; ++mi)
#pragma unroll
                for (int ni = 0; ni < 8; ++ni)
                    mma_tf32(d[mi][ni], a[mi], b[ni]);
        }
        st = (st + 1 >= 3) ? 0 : st + 1;
    }

    const float* wn_ptr = ((which == 0) ? qn_w : kn_w) + m * kHD;
#pragma unroll
    for (int mi = 0; mi < 2; ++mi) {
#pragma unroll
        for (int hh = 0; hh < 2; ++hh) {
            int iloc = rows + wm * 32 + mi * 16 + hh * 8 + lg;
            bool sel = (iloc < cnt);
            int row = idx[iloc];
            int c0 = hh * 2, c1 = hh * 2 + 1;
            if (which < 2) {
                float ss = 0.0f;
#pragma unroll
                for (int ni = 0; ni < 8; ++ni)
                    ss += d[mi][ni][c0] * d[mi][ni][c0] + d[mi][ni][c1] * d[mi][ni][c1];
                ss += __shfl_xor_sync(0xffffffffu, ss, 1);
                ss += __shfl_xor_sync(0xffffffffu, ss, 2);
                float sc = rsqrtf(ss * (1.0f / 64.0f) + kEps);
                if (sel) {
#pragma unroll
                    for (int ni = 0; ni < 8; ++ni) {
                        int cl = ni * 8 + lt * 2;
                        float2 o = {f2tf(d[mi][ni][c0] * sc * wn_ptr[cl]),
                                    f2tf(d[mi][ni][c1] * sc * wn_ptr[cl + 1])};
                        *(float2*)(Cout + (size_t)row * kE + cols + wn * 64 + cl) = o;
                    }
                }
            } else if (sel) {
#pragma unroll
                for (int ni = 0; ni < 8; ++ni) {
                    int cl = ni * 8 + lt * 2;
                    float2 o = {f2tf(d[mi][ni][c0]), f2tf(d[mi][ni][c1])};
                    *(float2*)(Cout + (size_t)row * kE + cols + wn * 64 + cl) = o;
                }
            }
        }
    }
}

// ---------------------------------------------------------------------------
// K2: flash attention (unchanged from R12: static-bound softmax)
// ---------------------------------------------------------------------------
__global__ __launch_bounds__(256, 2) void k_flash(const float* __restrict__ mask)
{
    extern __shared__ float sh[];
    float (*PQ)[68] = (float(*)[68])sh;
    float (*Kb)[64][68] = (float(*)[64][68])(sh + 128 * 68);
    float (*Vb)[64][72] = (float(*)[64][72])(sh + 256 * 68);

    const int bh = blockIdx.y;
    const int b = bh >> 4, h = bh & 15;
    const int qbase = blockIdx.x * 128;
    const int tid = threadIdx.x;
    const int wid = tid >> 5, lane = tid & 31;
    const int lg = lane >> 2, lt = lane & 3;
    const int mj = lane >> 3, mi2 = lane & 7;
    const int r0 = wid * 16;

    const float* qsrc = g_q + ((size_t)(b * kS + qbase)) * kE + h * kHD;
    const float* ksrc = g_k + ((size_t)(b * kS)) * kE + h * kHD;
    const float* vsrc = g_v + ((size_t)(b * kS)) * kE + h * kHD;

    const int lrow = tid >> 4;
    const int ld4  = (tid & 15) << 2;

#pragma unroll
    for (int rr = 0; rr < 8; ++rr) {
        int q = lrow + rr * 16;
        cpa16(&PQ[q][ld4], qsrc + (size_t)q * kE + ld4);
    }
    CPA_COMMIT();
#pragma unroll
    for (int rr = 0; rr < 4; ++rr) {
        int kc = lrow + rr * 16;
        cpa16(&Kb[0][kc][ld4], ksrc + (size_t)kc * kE + ld4);
        cpa16(&Vb[0][kc][ld4], vsrc + (size_t)kc * kE + ld4);
    }
    CPA_COMMIT();
    CPA_WAIT(1);
    __syncthreads();

    const uint32_t pa0 = sptr(&PQ[r0 + ((mj & 1) << 3) + mi2][(mj >> 1) << 2]);
    const uint32_t ka0 = sptr(&Kb[0][8 * (mj >> 1) + mi2][(mj & 1) << 2]);
    constexpr uint32_t KBUFB = 64 * 68 * 4;

    uint32_t qf[8][4];
#pragma unroll
    for (int c = 0; c < 8; ++c) ldsm4(qf[c], pa0 + c * 32);

    float oacc[8][4] = {};
    float lr[2] = {0.0f, 0.0f};
    const int qrow0 = qbase + r0 + lg;
    const int qrow1 = qrow0 + 8;
    const float B20 = g_mrow2[qrow0];
    const float B21 = g_mrow2[qrow1];
    constexpr float kSL2E = kScale * kL2E;

    for (int kbi = 0; kbi < kS / 64; ++kbi) {
        const int cur = kbi & 1;
        CPA_WAIT(0);
        __syncthreads();
        if (kbi + 1 < kS / 64) {
            const int nxt = cur ^ 1;
            const size_t koff = (size_t)(kbi + 1) * 64;
#pragma unroll
            for (int rr = 0; rr < 4; ++rr) {
                int kc = lrow + rr * 16;
                cpa16(&Kb[nxt][kc][ld4], ksrc + (koff + kc) * kE + ld4);
                cpa16(&Vb[nxt][kc][ld4], vsrc + (koff + kc) * kE + ld4);
            }
            CPA_COMMIT();
        }

        float s[8][4] = {};
        const uint32_t kcur = ka0 + cur * KBUFB;
#pragma unroll
        for (int c = 0; c < 8; ++c) {
            const uint32_t kc4 = kcur + c * 32;
#pragma unroll
            for (int t = 0; t < 4; ++t) {
                uint32_t bb[4];
                ldsm4(bb, kc4 + t * (16 * 68 * 4));
                mma_tf32(s[2 * t],     qf[c], bb);
                mma_tf32(s[2 * t + 1], qf[c], bb + 2);
            }
        }

        const int kb = kbi * 64;
#pragma unroll
        for (int ni = 0; ni < 8; ++ni) {
            size_t col = (size_t)kb + ni * 8 + lt * 2;
            float2 m0 = *(const float2*)(mask + (size_t)qrow0 * kS + col);
            float2 m1 = *(const float2*)(mask + (size_t)qrow1 * kS + col);
            s[ni][0] = ex2(fmaf(s[ni][0], kSL2E, fmaf(m0.x, kL2E, -B20)));
            s[ni][1] = ex2(fmaf(s[ni][1], kSL2E, fmaf(m0.y, kL2E, -B20)));
            s[ni][2] = ex2(fmaf(s[ni][2], kSL2E, fmaf(m1.x, kL2E, -B21)));
            s[ni][3] = ex2(fmaf(s[ni][3], kSL2E, fmaf(m1.y, kL2E, -B21)));
            lr[0] += s[ni][0] + s[ni][1];
            lr[1] += s[ni][2] + s[ni][3];
        }

#pragma unroll
        for (int ni = 0; ni < 8; ++ni) {
            int cl = ni * 8 + lt * 2;
            float2 p0 = {f2tf(s[ni][0]), f2tf(s[ni][1])};
            float2 p1 = {f2tf(s[ni][2]), f2tf(s[ni][3])};
            *(float2*)&PQ[r0 + lg][cl] = p0;
            *(float2*)&PQ[r0 + 8 + lg][cl] = p1;
        }
        __syncwarp();

#pragma unroll
        for (int c = 0; c < 8; ++c) {
            int ks = c * 8;
            uint32_t a[4];
            ldsm4(a, pa0 + c * 32);
#pragma unroll
            for (int ni = 0; ni < 8; ++ni) {
                uint32_t bfr[2];
                bfr[0] = fu(Vb[cur][ks + lt][ni * 8 + lg]);
                bfr[1] = fu(Vb[cur][ks + 4 + lt][ni * 8 + lg]);
                mma_tf32(oacc[ni], a, bfr);
            }
        }
    }

    lr[0] += __shfl_xor_sync(0xffffffffu, lr[0], 1);
    lr[0] += __shfl_xor_sync(0xffffffffu, lr[0], 2);
    lr[1] += __shfl_xor_sync(0xffffffffu, lr[1], 1);
    lr[1] += __shfl_xor_sync(0xffffffffu, lr[1], 2);

    float il0 = 1.0f / lr[0], il1 = 1.0f / lr[1];
#pragma unroll
    for (int ni = 0; ni < 8; ++ni) {
        int cl = ni * 8 + lt * 2;
        float2 o0 = {f2tf(oacc[ni][0] * il0), f2tf(oacc[ni][1] * il0)};
        float2 o1 = {f2tf(oacc[ni][2] * il1), f2tf(oacc[ni][3] * il1)};
        *(float2*)(g_ctx + (size_t)(b * kS + qrow0) * kE + h * kHD + cl) = o0;
        *(float2*)(g_ctx + (size_t)(b * kS + qrow1) * kE + h * kHD + cl) = o1;
    }
    if (lt == 0) {
        size_t i0 = ((size_t)bh * kS + qrow0) * 2;
        size_t i1 = ((size_t)bh * kS + qrow1) * 2;
        g_ml[i0] = B20; g_ml[i0 + 1] = lr[0];
        g_ml[i1] = B21; g_ml[i1 + 1] = lr[1];
    }
}

// ---------------------------------------------------------------------------
// K3: attn_weights (unchanged from R12)
// ---------------------------------------------------------------------------
__global__ __launch_bounds__(256, 2) void k_attnw(const float* __restrict__ mask,
                                                  float* __restrict__ aw_out)
{
    extern __shared__ float sh[];
    float (*Qb)[128][68] = (float(*)[128][68])sh;
    float (*Kb)[64][68]  = (float(*)[64][68])(sh + 2 * 128 * 68);

    const int b = blockIdx.z;
    const int qbase = blockIdx.y * 128;
    const int kbase = blockIdx.x * 64;
    const int tid = threadIdx.x;
    const int wid = tid >> 5, lane = tid & 31;
    const int lg = lane >> 2, lt = lane & 3;
    const int mj = lane >> 3, mi2 = lane & 7;
    const int r0 = wid * 16;
    const int qrow0 = qbase + r0 + lg;
    const int qrow1 = qrow0 + 8;

    const float* qsrc = g_q + ((size_t)(b * kS + qbase)) * kE;
    const float* ksrc = g_k + ((size_t)(b * kS + kbase)) * kE;
    const int lrow = tid >> 4;
    const int ld4  = (tid & 15) << 2;

#pragma unroll
    for (int rr = 0; rr < 8; ++rr) {
        int q = lrow + rr * 16;
        cpa16(&Qb[0][q][ld4], qsrc + (size_t)q * kE + ld4);
    }
#pragma unroll
    for (int rr = 0; rr < 4; ++rr) {
        int kc = lrow + rr * 16;
        cpa16(&Kb[0][kc][ld4], ksrc + (size_t)kc * kE + ld4);
    }
    CPA_COMMIT();

    const uint32_t qa0 = sptr(&Qb[0][r0 + ((mj & 1) << 3) + mi2][(mj >> 1) << 2]);
    const uint32_t ka0 = sptr(&Kb[0][8 * (mj >> 1) + mi2][(mj & 1) << 2]);
    constexpr uint32_t QBUFB = 128 * 68 * 4;
    constexpr uint32_t KBUFB = 64 * 68 * 4;

    float mk2[8][4];
#pragma unroll
    for (int ni = 0; ni < 8; ++ni) {
        size_t col = (size_t)kbase + ni * 8 + lt * 2;
        float2 m0 = *(const float2*)(mask + (size_t)qrow0 * kS + col);
        float2 m1 = *(const float2*)(mask + (size_t)qrow1 * kS + col);
        mk2[ni][0] = m0.x * kL2E; mk2[ni][1] = m0.y * kL2E;
        mk2[ni][2] = m1.x * kL2E; mk2[ni][3] = m1.y * kL2E;
    }

    const float* mlp = g_ml + ((size_t)b * kH) * kS * 2;
    float2 mlA0 = *(const float2*)(mlp + (size_t)qrow0 * 2);
    float2 mlA1 = *(const float2*)(mlp + (size_t)qrow1 * 2);

    constexpr float kSL2E = kScale * kL2E;
    float aw[8][4] = {};

    for (int h = 0; h < kH; ++h) {
        const int cur = h & 1;
        CPA_WAIT(0);
        __syncthreads();
        if (h + 1 < kH) {
            const int nxt = cur ^ 1;
            const size_t hoff = (size_t)(h + 1) * kHD;
#pragma unroll
            for (int rr = 0; rr < 8; ++rr) {
                int q = lrow + rr * 16;
                cpa16(&Qb[nxt][q][ld4], qsrc + (size_t)q * kE + hoff + ld4);
            }
#pragma unroll
            for (int rr = 0; rr < 4; ++rr) {
                int kc = lrow + rr * 16;
                cpa16(&Kb[nxt][kc][ld4], ksrc + (size_t)kc * kE + hoff + ld4);
            }
            CPA_COMMIT();
        }

        float2 mlB0, mlB1;
        if (h + 1 < kH) {
            mlB0 = *(const float2*)(mlp + ((size_t)(h + 1) * kS + qrow0) * 2);
            mlB1 = *(const float2*)(mlp + ((size_t)(h + 1) * kS + qrow1) * 2);
        }

        float s[8][4] = {};
        const uint32_t qcur = qa0 + cur * QBUFB;
        const uint32_t kcur = ka0 + cur * KBUFB;
#pragma unroll
        for (int c = 0; c < 8; ++c) {
            uint32_t a[4];
            ldsm4(a, qcur + c * 32);
            const uint32_t kc4 = kcur + c * 32;
#pragma unroll
            for (int t = 0; t < 4; ++t) {
                uint32_t bb[4];
                ldsm4(bb, kc4 + t * (16 * 68 * 4));
                mma_tf32(s[2 * t],     a, bb);
                mma_tf32(s[2 * t + 1], a, bb + 2);
            }
        }

        float c20 = mlA0.x + __log2f(mlA0.y);
        float c21 = mlA1.x + __log2f(mlA1.y);
#pragma unroll
        for (int ni = 0; ni < 8; ++ni) {
            aw[ni][0] += ex2(fmaf(s[ni][0], kSL2E, mk2[ni][0]) - c20);
            aw[ni][1] += ex2(fmaf(s[ni][1], kSL2E, mk2[ni][1]) - c20);
            aw[ni][2] += ex2(fmaf(s[ni][2], kSL2E, mk2[ni][2]) - c21);
            aw[ni][3] += ex2(fmaf(s[ni][3], kSL2E, mk2[ni][3]) - c21);
        }
        mlA0 = mlB0;
        mlA1 = mlB1;
    }

#pragma unroll
    for (int ni = 0; ni < 8; ++ni) {
        int col = kbase + ni * 8 + lt * 2;
        float2 o0 = {aw[ni][0] * (1.0f / kH), aw[ni][1] * (1.0f / kH)};
        float2 o1 = {aw[ni][2] * (1.0f / kH), aw[ni][3] * (1.0f / kH)};
        *(float2*)(aw_out + (size_t)b * kS * kS + (size_t)qrow0 * kS + col) = o0;
        *(float2*)(aw_out + (size_t)b * kS * kS + (size_t)qrow1 * kS + col) = o1;
    }
}

// ---------------------------------------------------------------------------
// K4: output projection, 3-stage cp.async pipeline (wait_group 1)
// ---------------------------------------------------------------------------
__global__ __launch_bounds__(256) void k_oproj()
{
    extern __shared__ float sh[];
    const int m = blockIdx.z;
    const int cnt = g_cnt[m];
    const int rows = blockIdx.y * 128;
    if (rows >= cnt) return;

    const float* W = g_wo + (size_t)m * kE * kD;
    const int* idx = g_idx + m * kNR;

    const int tid = threadIdx.x;
    const int wid = tid >> 5, lane = tid & 31;
    const int lg = lane >> 2, lt = lane & 3;
    const int mj = lane >> 3, mi2 = lane & 7;
    const int wm = wid & 3, wn = wid >> 2;
    const int cols = blockIdx.x * 128;

    float d[2][8][4] = {};

    const int arow = tid >> 3;
    const int ac4  = (tid & 7) << 2;
    const float* aptr[4];
#pragma unroll
    for (int i = 0; i < 4; ++i)
        aptr[i] = g_ctx + (size_t)idx[rows + arow + 32 * i] * kE + ac4;
    const int brow = tid >> 5;
    const int bc4  = (tid & 31) << 2;
    const float* bptr = W + (size_t)brow * kD + cols + bc4;

    uint32_t aabase[3];
#pragma unroll
    for (int st = 0; st < 3; ++st)
        aabase[st] = sptr(sh + st * 4608 +
                          (wm * 32 + ((mj & 1) << 3) + mi2) * 36 + ((mj >> 1) << 2));

    auto issue = [&](int st, int k0) {
        float* as = sh + st * 4608;
        float* bs = sh + 13824 + st * 4352;
#pragma unroll
        for (int i = 0; i < 4; ++i)
            cpa16(as + (arow + 32 * i) * 36 + ac4, aptr[i] + k0);
#pragma unroll
        for (int i = 0; i < 4; ++i)
            cpa16(bs + (brow + 8 * i) * 136 + bc4, bptr + (size_t)(k0 + 8 * i) * kD);
    };

    issue(0, 0);  CPA_COMMIT();
    issue(1, 32); CPA_COMMIT();

    constexpr int NIT = kE / 32;
    int st = 0;
    for (int kb = 0; kb < NIT; ++kb) {
        CPA_WAIT(1);
        __syncthreads();
        if (kb + 2 < NIT) {
            int nst = (st + 2 >= 3) ? st - 1 : st + 2;
            issue(nst, (kb + 2) * 32);
            CPA_COMMIT();
        }

        const float* bs = sh + 13824 + st * 4352;
#pragma unroll
        for (int ks = 0; ks < 32; ks += 8) {
            uint32_t a[2][4], b[8][2];
            ldsm4(a[0], aabase[st] + ks * 4);
            ldsm4(a[1], aabase[st] + 2304 + ks * 4);
#pragma unroll
            for (int ni = 0; ni < 8; ++ni) {
                int n = wn * 64 + ni * 8 + lg;
                b[ni][0] = fu(bs[(ks + lt) * 136 + n]);
                b[ni][1] = fu(bs[(ks + 4 + lt) * 136 + n]);
            }
#pragma unroll
            for (int mi = 0; mi < 2; ++mi)
#pragma unroll
                for (int ni = 0; ni < 8; ++ni)
                    mma_tf32(d[mi][ni], a[mi], b[ni]);
        }
        st = (st + 1 >= 3) ? 0 : st + 1;
    }

#pragma unroll
    for (int mi = 0; mi < 2; ++mi) {
#pragma unroll
        for (int hh = 0; hh < 2; ++hh) {
            int iloc = rows + wm * 32 + mi * 16 + hh * 8 + lg;
            if (iloc < cnt) {
                int row = idx[iloc];
                int c0 = hh * 2, c1 = hh * 2 + 1;
#pragma unroll
                for (int ni = 0; ni < 8; ++ni) {
                    int cl = ni * 8 + lt * 2;
                    float2 o = {d[mi][ni][c0], d[mi][ni][c1]};
                    *(float2*)(g_o + (size_t)row * kD + cols + wn * 64 + cl) = o;
                }
            }
        }
    }
}

// ---------------------------------------------------------------------------
// K5: final full-row RMSNorm (fp32)
// ---------------------------------------------------------------------------
__global__ __launch_bounds__(256) void k_rmsout(const int* __restrict__ mod_ids,
                                                const float* __restrict__ anw,
                                                float* __restrict__ out)
{
    const int rg = blockIdx.x;
    const int tid = threadIdx.x;
    const int mid = mod_ids[rg];
    const float* src = g_o + (size_t)rg * kD;

    float4 v = *(const float4*)(src + tid * 4);
    float ss = v.x * v.x + v.y * v.y + v.z * v.z + v.w * v.w;
#pragma unroll
    for (int off = 16; off > 0; off >>= 1)
        ss += __shfl_xor_sync(0xffffffffu, ss, off);

    __shared__ float red[8];
    __shared__ float scale_sh;
    if ((tid & 31) == 0) red[tid >> 5] = ss;
    __syncthreads();
    if (tid == 0) {
        float t = 0.0f;
#pragma unroll
        for (int w = 0; w < 8; ++w) t += red[w];
        scale_sh = rsqrtf(t * (1.0f / kD) + kEps);
    }
    __syncthreads();
    float sc = scale_sh;

    const float* w = anw + (size_t)mid * kD;
    float4 w4 = *(const float4*)(w + tid * 4);
    float4 o = {v.x * sc * w4.x, v.y * sc * w4.y, v.z * sc * w4.z, v.w * sc * w4.w};
    *(float4*)(out + (size_t)rg * kD + tid * 4) = o;
}

// ---------------------------------------------------------------------------
extern "C" void kernel_launch(void* const* d_in, const int* in_sizes, int n_in,
                              void* d_out, int out_size)
{
    const float* x         = (const float*)d_in[0];
    const float* attn_mask = (const float*)d_in[1];
    const int*   mod_ids   = (const int*)d_in[2];
    const float* Wq        = (const float*)d_in[3];
    const float* Wk        = (const float*)d_in[4];
    const float* Wv        = (const float*)d_in[5];
    const float* Wo        = (const float*)d_in[6];
    const float* qn_w      = (const float*)d_in[7];
    const float* kn_w      = (const float*)d_in[8];
    const float* anw       = (const float*)d_in[9];

    float* out = (float*)d_out;
    float* aw  = out + (size_t)kNR * kD;

    constexpr int kGemmSmem  = 26880 * 4;                              // 107520
    constexpr int kFlashSmem = (128 * 68 + 2 * 64 * 68 + 2 * 64 * 72) * 4;  // 106496
    constexpr int kAttnwSmem = 384 * 68 * 4;                           // 104448
    cudaFuncSetAttribute(k_qkv,   cudaFuncAttributeMaxDynamicSharedMemorySize, kGemmSmem);
    cudaFuncSetAttribute(k_oproj, cudaFuncAttributeMaxDynamicSharedMemorySize, kGemmSmem);
    cudaFuncSetAttribute(k_flash, cudaFuncAttributeMaxDynamicSharedMemorySize, kFlashSmem);
    cudaFuncSetAttribute(k_attnw, cudaFuncAttributeMaxDynamicSharedMemorySize, kAttnwSmem);

    dim3 blk(256);
    constexpr int nTot4 = (kNR * kD + 4 * kM * kD * kE) / 4;
    k_round_all<<<nTot4 / 256, blk>>>(x, Wq, Wk, Wv, Wo);
    k_mrow<<<kS, blk>>>(attn_mask);
    k_compact<<<1, 1024>>>(mod_ids);
    k_qkv  <<<dim3(kE / 128, kNR / 128, 6), blk, kGemmSmem>>>(qn_w, kn_w);
    k_flash<<<dim3(kS / 128, kB * kH), blk, kFlashSmem>>>(attn_mask);
    k_attnw<<<dim3(kS / 64, kS / 128, kB), blk, kAttnwSmem>>>(attn_mask, aw);
    k_oproj<<<dim3(kD / 128, kNR / 128, kM), blk, kGemmSmem>>>();
    k_rmsout<<<kNR, blk>>>(mod_ids, anw, out);
}

// round 14
// speedup vs baseline: 1.5523x; 1.5523x over previous
#include <cuda_runtime.h>
#include <cstdint>

// ---------------------------------------------------------------------------
// SimpleModalityUntiedAttention: B=2 S=2048 D=1024 H=16 HD=64 M=2 E=1024
// Round 14: revert to R12 2-stage GEMM pipelines; weights stored TRANSPOSED
// (k_wtrans) so GEMM B-fragments load via ldmatrix (64 LDS.32 -> 16 LDSM
// per k-block). flash/attnw identical to R12.
// ---------------------------------------------------------------------------

namespace {
constexpr int kB  = 2;
constexpr int kS  = 2048;
constexpr int kD  = 1024;
constexpr int kH  = 16;
constexpr int kHD = 64;
constexpr int kM  = 2;
constexpr int kE  = 1024;
constexpr int kNR = kB * kS;
constexpr float kEps   = 1e-5f;
constexpr float kScale = 0.125f;
constexpr float kL2E   = 1.44269504088896340736f;
}

__device__ float g_q[kNR * kE];
__device__ float g_k[kNR * kE];
__device__ float g_v[kNR * kE];
__device__ float g_ctx[kNR * kE];
__device__ float g_o[kNR * kD];
__device__ float g_ml[kB * kH * kS * 2];   // (B2 log2 units, sumexp)
__device__ float g_mrow2[kS];
__device__ int   g_idx[kM * kNR];
__device__ int   g_cnt[kM];
__device__ float g_xr[kNR * kD];
// TRANSPOSED tf32-rounded weights: [m][n][k]
__device__ float g_wq[kM * kD * kE];
__device__ float g_wk[kM * kD * kE];
__device__ float g_wv[kM * kD * kE];
__device__ float g_wo[kM * kE * kD];

__device__ __forceinline__ float f2tf(float x) {
    uint32_t u;
    asm("cvt.rna.tf32.f32 %0, %1;" : "=r"(u) : "f"(x));
    return __uint_as_float(u);
}
__device__ __forceinline__ uint32_t fu(float x) { return __float_as_uint(x); }
__device__ __forceinline__ float ex2(float x) {
    float r;
    asm("ex2.approx.f32 %0, %1;" : "=f"(r) : "f"(x));
    return r;
}

__device__ __forceinline__ void mma_tf32(float* d, const uint32_t* a, const uint32_t* b) {
    asm volatile(
        "mma.sync.aligned.m16n8k8.row.col.f32.tf32.tf32.f32 "
        "{%0,%1,%2,%3}, {%4,%5,%6,%7}, {%8,%9}, {%0,%1,%2,%3};"
        : "+f"(d[0]), "+f"(d[1]), "+f"(d[2]), "+f"(d[3])
        : "r"(a[0]), "r"(a[1]), "r"(a[2]), "r"(a[3]), "r"(b[0]), "r"(b[1]));
}

__device__ __forceinline__ void ldsm4(uint32_t* r, uint32_t saddr) {
    asm volatile("ldmatrix.sync.aligned.m8n8.x4.shared.b16 {%0,%1,%2,%3}, [%4];"
        : "=r"(r[0]), "=r"(r[1]), "=r"(r[2]), "=r"(r[3]) : "r"(saddr));
}
__device__ __forceinline__ uint32_t sptr(const void* p) {
    return (uint32_t)__cvta_generic_to_shared(p);
}

__device__ __forceinline__ void cpa16(void* dst_smem, const void* src) {
    uint32_t d = (uint32_t)__cvta_generic_to_shared(dst_smem);
    asm volatile("cp.async.cg.shared.global [%0], [%1], 16;" :: "r"(d), "l"(src));
}
#define CPA_COMMIT() asm volatile("cp.async.commit_group;")
#define CPA_WAIT(N)  asm volatile("cp.async.wait_group %0;" :: "n"(N))

// ---------------------------------------------------------------------------
// K-1a: tf32 round-copy of x
// ---------------------------------------------------------------------------
__global__ __launch_bounds__(256) void k_round_x(const float* __restrict__ x)
{
    int i = blockIdx.x * 256 + threadIdx.x;
    float4 v = ((const float4*)x)[i];
    float4 r = {f2tf(v.x), f2tf(v.y), f2tf(v.z), f2tf(v.w)};
    ((float4*)g_xr)[i] = r;
}

// ---------------------------------------------------------------------------
// K-1b: transpose + tf32-round all 8 weight matrices (32x33 smem tiles).
// z = tensor*2 + m. Output layout [n][k].
// ---------------------------------------------------------------------------
__global__ __launch_bounds__(256) void k_wtrans(
    const float* __restrict__ Wq, const float* __restrict__ Wk,
    const float* __restrict__ Wv, const float* __restrict__ Wo)
{
    __shared__ float t[32][33];
    const int z = blockIdx.z;
    const int tsr = z >> 1, m = z & 1;
    const float* src = ((tsr == 0) ? Wq : (tsr == 1) ? Wk : (tsr == 2) ? Wv : Wo)
                       + (size_t)m * kD * kE;
    float* dst = ((tsr == 0) ? g_wq : (tsr == 1) ? g_wk : (tsr == 2) ? g_wv : g_wo)
                 + (size_t)m * kD * kE;
    const int k0 = blockIdx.y * 32, n0 = blockIdx.x * 32;
    const int tx = threadIdx.x & 31, ty = threadIdx.x >> 5;
#pragma unroll
    for (int r = 0; r < 4; ++r)
        t[ty + r * 8][tx] = f2tf(src[(size_t)(k0 + ty + r * 8) * 1024 + n0 + tx]);
    __syncthreads();
#pragma unroll
    for (int r = 0; r < 4; ++r)
        dst[(size_t)(n0 + ty + r * 8) * 1024 + k0 + tx] = t[tx][ty + r * 8];
}

// ---------------------------------------------------------------------------
// K-2: per-row mask max -> static softmax bound B2(q)
// ---------------------------------------------------------------------------
__global__ __launch_bounds__(256) void k_mrow(const float* __restrict__ mask)
{
    const int q = blockIdx.x;
    const int tid = threadIdx.x;
    float m = -3e38f;
    const float* row = mask + (size_t)q * kS;
    for (int k = tid; k < kS; k += 256) m = fmaxf(m, row[k]);
#pragma unroll
    for (int off = 16; off > 0; off >>= 1)
        m = fmaxf(m, __shfl_xor_sync(0xffffffffu, m, off));
    __shared__ float red[8];
    if ((tid & 31) == 0) red[tid >> 5] = m;
    __syncthreads();
    if (tid == 0) {
        float t = red[0];
#pragma unroll
        for (int w = 1; w < 8; ++w) t = fmaxf(t, red[w]);
        g_mrow2[q] = (8.25f + t) * kL2E;
    }
}

// ---------------------------------------------------------------------------
// K0: modality compaction
// ---------------------------------------------------------------------------
__global__ __launch_bounds__(1024) void k_compact(const int* __restrict__ mod_ids)
{
    __shared__ int cnt[kM];
    const int tid = threadIdx.x;
    if (tid < kM) cnt[tid] = 0;
    __syncthreads();
    for (int r = tid; r < kNR; r += 1024) {
        int m = mod_ids[r];
        int pos = atomicAdd(&cnt[m], 1);
        g_idx[m * kNR + pos] = r;
    }
    __syncthreads();
    int c0 = cnt[0], c1 = cnt[1];
    if (tid == 0) { g_cnt[0] = c0; g_cnt[1] = c1; }
    for (int i = c0 + tid; i < kNR; i += 1024) g_idx[i] = 0;
    for (int i = c1 + tid; i < kNR; i += 1024) g_idx[kNR + i] = 0;
}

// ---------------------------------------------------------------------------
// GEMM smem (floats): As[st][128][36] at st*4608, BsT[st][128][36] at
// 9216 + st*4608. Total 18432 fl = 73728 B. 2-stage.
// ---------------------------------------------------------------------------

// ---------------------------------------------------------------------------
// K1: QKV projection; A and B^T both ldmatrix-fed, 2-stage cp.async.
// ---------------------------------------------------------------------------
__global__ __launch_bounds__(256) void k_qkv(
    const float* __restrict__ qn_w, const float* __restrict__ kn_w)
{
    extern __shared__ float sh[];
    const int z = blockIdx.z;
    const int m = z / 3;
    const int which = z % 3;
    const int cnt = g_cnt[m];
    const int rows = blockIdx.y * 128;
    if (rows >= cnt) return;

    const float* Wt = ((which == 0) ? g_wq : (which == 1) ? g_wk : g_wv)
                      + (size_t)m * kD * kE;          // [n][k]
    float* Cout = (which == 0) ? g_q : (which == 1) ? g_k : g_v;
    const int* idx = g_idx + m * kNR;

    const int tid = threadIdx.x;
    const int wid = tid >> 5, lane = tid & 31;
    const int lg = lane >> 2, lt = lane & 3;
    const int mj = lane >> 3, mi2 = lane & 7;
    const int wm = wid & 3, wn = wid >> 2;
    const int cols = blockIdx.x * 128;

    float d[2][8][4] = {};

    const int arow = tid >> 3;            // 0..31
    const int ac4  = (tid & 7) << 2;      // 0..28
    const float* aptr[4];
    const float* bptr[4];
#pragma unroll
    for (int i = 0; i < 4; ++i) {
        aptr[i] = g_xr + (size_t)idx[rows + arow + 32 * i] * kD + ac4;
        bptr[i] = Wt + (size_t)(cols + arow + 32 * i) * kE + ac4;
    }

    uint32_t aabase[2], bbbase[2];
#pragma unroll
    for (int st = 0; st < 2; ++st) {
        aabase[st] = sptr(sh + st * 4608 +
                          (wm * 32 + ((mj & 1) << 3) + mi2) * 36 + ((mj >> 1) << 2));
        bbbase[st] = sptr(sh + 9216 + st * 4608 +
                          (wn * 64 + 8 * (mj >> 1) + mi2) * 36 + ((mj & 1) << 2));
    }

    auto issue = [&](int st, int k0) {
        float* as = sh + st * 4608;
        float* bs = sh + 9216 + st * 4608;
#pragma unroll
        for (int i = 0; i < 4; ++i) {
            cpa16(as + (arow + 32 * i) * 36 + ac4, aptr[i] + k0);
            cpa16(bs + (arow + 32 * i) * 36 + ac4, bptr[i] + k0);
        }
    };

    issue(0, 0);
    CPA_COMMIT();

    constexpr int NIT = kD / 32;
    for (int kb = 0; kb < NIT; ++kb) {
        const int cur = kb & 1;
        CPA_WAIT(0);
        __syncthreads();
        if (kb + 1 < NIT) { issue(cur ^ 1, (kb + 1) * 32); CPA_COMMIT(); }

#pragma unroll
        for (int ks = 0; ks < 32; ks += 8) {
            uint32_t a[2][4];
            ldsm4(a[0], aabase[cur] + ks * 4);
            ldsm4(a[1], aabase[cur] + 2304 + ks * 4);
#pragma unroll
            for (int t = 0; t < 4; ++t) {
                uint32_t bb[4];
                ldsm4(bb, bbbase[cur] + t * 2304 + ks * 4);
                mma_tf32(d[0][2 * t],     a[0], bb);
                mma_tf32(d[0][2 * t + 1], a[0], bb + 2);
                mma_tf32(d[1][2 * t],     a[1], bb);
                mma_tf32(d[1][2 * t + 1], a[1], bb + 2);
            }
        }
    }

    const float* wn_ptr = ((which == 0) ? qn_w : kn_w) + m * kHD;
#pragma unroll
    for (int mi = 0; mi < 2; ++mi) {
#pragma unroll
        for (int hh = 0; hh < 2; ++hh) {
            int iloc = rows + wm * 32 + mi * 16 + hh * 8 + lg;
            bool sel = (iloc < cnt);
            int row = idx[iloc];
            int c0 = hh * 2, c1 = hh * 2 + 1;
            if (which < 2) {
                float ss = 0.0f;
#pragma unroll
                for (int ni = 0; ni < 8; ++ni)
                    ss += d[mi][ni][c0] * d[mi][ni][c0] + d[mi][ni][c1] * d[mi][ni][c1];
                ss += __shfl_xor_sync(0xffffffffu, ss, 1);
                ss += __shfl_xor_sync(0xffffffffu, ss, 2);
                float sc = rsqrtf(ss * (1.0f / 64.0f) + kEps);
                if (sel) {
#pragma unroll
                    for (int ni = 0; ni < 8; ++ni) {
                        int cl = ni * 8 + lt * 2;
                        float2 o = {f2tf(d[mi][ni][c0] * sc * wn_ptr[cl]),
                                    f2tf(d[mi][ni][c1] * sc * wn_ptr[cl + 1])};
                        *(float2*)(Cout + (size_t)row * kE + cols + wn * 64 + cl) = o;
                    }
                }
            } else if (sel) {
#pragma unroll
                for (int ni = 0; ni < 8; ++ni) {
                    int cl = ni * 8 + lt * 2;
                    float2 o = {f2tf(d[mi][ni][c0]), f2tf(d[mi][ni][c1])};
                    *(float2*)(Cout + (size_t)row * kE + cols + wn * 64 + cl) = o;
                }
            }
        }
    }
}

// ---------------------------------------------------------------------------
// K2: flash attention (unchanged from R12: static-bound softmax)
// ---------------------------------------------------------------------------
__global__ __launch_bounds__(256, 2) void k_flash(const float* __restrict__ mask)
{
    extern __shared__ float sh[];
    float (*PQ)[68] = (float(*)[68])sh;
    float (*Kb)[64][68] = (float(*)[64][68])(sh + 128 * 68);
    float (*Vb)[64][72] = (float(*)[64][72])(sh + 256 * 68);

    const int bh = blockIdx.y;
    const int b = bh >> 4, h = bh & 15;
    const int qbase = blockIdx.x * 128;
    const int tid = threadIdx.x;
    const int wid = tid >> 5, lane = tid & 31;
    const int lg = lane >> 2, lt = lane & 3;
    const int mj = lane >> 3, mi2 = lane & 7;
    const int r0 = wid * 16;

    const float* qsrc = g_q + ((size_t)(b * kS + qbase)) * kE + h * kHD;
    const float* ksrc = g_k + ((size_t)(b * kS)) * kE + h * kHD;
    const float* vsrc = g_v + ((size_t)(b * kS)) * kE + h * kHD;

    const int lrow = tid >> 4;
    const int ld4  = (tid & 15) << 2;

#pragma unroll
    for (int rr = 0; rr < 8; ++rr) {
        int q = lrow + rr * 16;
        cpa16(&PQ[q][ld4], qsrc + (size_t)q * kE + ld4);
    }
    CPA_COMMIT();
#pragma unroll
    for (int rr = 0; rr < 4; ++rr) {
        int kc = lrow + rr * 16;
        cpa16(&Kb[0][kc][ld4], ksrc + (size_t)kc * kE + ld4);
        cpa16(&Vb[0][kc][ld4], vsrc + (size_t)kc * kE + ld4);
    }
    CPA_COMMIT();
    CPA_WAIT(1);
    __syncthreads();

    const uint32_t pa0 = sptr(&PQ[r0 + ((mj & 1) << 3) + mi2][(mj >> 1) << 2]);
    const uint32_t ka0 = sptr(&Kb[0][8 * (mj >> 1) + mi2][(mj & 1) << 2]);
    constexpr uint32_t KBUFB = 64 * 68 * 4;

    uint32_t qf[8][4];
#pragma unroll
    for (int c = 0; c < 8; ++c) ldsm4(qf[c], pa0 + c * 32);

    float oacc[8][4] = {};
    float lr[2] = {0.0f, 0.0f};
    const int qrow0 = qbase + r0 + lg;
    const int qrow1 = qrow0 + 8;
    const float B20 = g_mrow2[qrow0];
    const float B21 = g_mrow2[qrow1];
    constexpr float kSL2E = kScale * kL2E;

    for (int kbi = 0; kbi < kS / 64; ++kbi) {
        const int cur = kbi & 1;
        CPA_WAIT(0);
        __syncthreads();
        if (kbi + 1 < kS / 64) {
            const int nxt = cur ^ 1;
            const size_t koff = (size_t)(kbi + 1) * 64;
#pragma unroll
            for (int rr = 0; rr < 4; ++rr) {
                int kc = lrow + rr * 16;
                cpa16(&Kb[nxt][kc][ld4], ksrc + (koff + kc) * kE + ld4);
                cpa16(&Vb[nxt][kc][ld4], vsrc + (koff + kc) * kE + ld4);
            }
            CPA_COMMIT();
        }

        float s[8][4] = {};
        const uint32_t kcur = ka0 + cur * KBUFB;
#pragma unroll
        for (int c = 0; c < 8; ++c) {
            const uint32_t kc4 = kcur + c * 32;
#pragma unroll
            for (int t = 0; t < 4; ++t) {
                uint32_t bb[4];
                ldsm4(bb, kc4 + t * (16 * 68 * 4));
                mma_tf32(s[2 * t],     qf[c], bb);
                mma_tf32(s[2 * t + 1], qf[c], bb + 2);
            }
        }

        const int kb = kbi * 64;
#pragma unroll
        for (int ni = 0; ni < 8; ++ni) {
            size_t col = (size_t)kb + ni * 8 + lt * 2;
            float2 m0 = *(const float2*)(mask + (size_t)qrow0 * kS + col);
            float2 m1 = *(const float2*)(mask + (size_t)qrow1 * kS + col);
            s[ni][0] = ex2(fmaf(s[ni][0], kSL2E, fmaf(m0.x, kL2E, -B20)));
            s[ni][1] = ex2(fmaf(s[ni][1], kSL2E, fmaf(m0.y, kL2E, -B20)));
            s[ni][2] = ex2(fmaf(s[ni][2], kSL2E, fmaf(m1.x, kL2E, -B21)));
            s[ni][3] = ex2(fmaf(s[ni][3], kSL2E, fmaf(m1.y, kL2E, -B21)));
            lr[0] += s[ni][0] + s[ni][1];
            lr[1] += s[ni][2] + s[ni][3];
        }

#pragma unroll
        for (int ni = 0; ni < 8; ++ni) {
            int cl = ni * 8 + lt * 2;
            float2 p0 = {f2tf(s[ni][0]), f2tf(s[ni][1])};
            float2 p1 = {f2tf(s[ni][2]), f2tf(s[ni][3])};
            *(float2*)&PQ[r0 + lg][cl] = p0;
            *(float2*)&PQ[r0 + 8 + lg][cl] = p1;
        }
        __syncwarp();

#pragma unroll
        for (int c = 0; c < 8; ++c) {
            int ks = c * 8;
            uint32_t a[4];
            ldsm4(a, pa0 + c * 32);
#pragma unroll
            for (int ni = 0; ni < 8; ++ni) {
                uint32_t bfr[2];
                bfr[0] = fu(Vb[cur][ks + lt][ni * 8 + lg]);
                bfr[1] = fu(Vb[cur][ks + 4 + lt][ni * 8 + lg]);
                mma_tf32(oacc[ni], a, bfr);
            }
        }
    }

    lr[0] += __shfl_xor_sync(0xffffffffu, lr[0], 1);
    lr[0] += __shfl_xor_sync(0xffffffffu, lr[0], 2);
    lr[1] += __shfl_xor_sync(0xffffffffu, lr[1], 1);
    lr[1] += __shfl_xor_sync(0xffffffffu, lr[1], 2);

    float il0 = 1.0f / lr[0], il1 = 1.0f / lr[1];
#pragma unroll
    for (int ni = 0; ni < 8; ++ni) {
        int cl = ni * 8 + lt * 2;
        float2 o0 = {f2tf(oacc[ni][0] * il0), f2tf(oacc[ni][1] * il0)};
        float2 o1 = {f2tf(oacc[ni][2] * il1), f2tf(oacc[ni][3] * il1)};
        *(float2*)(g_ctx + (size_t)(b * kS + qrow0) * kE + h * kHD + cl) = o0;
        *(float2*)(g_ctx + (size_t)(b * kS + qrow1) * kE + h * kHD + cl) = o1;
    }
    if (lt == 0) {
        size_t i0 = ((size_t)bh * kS + qrow0) * 2;
        size_t i1 = ((size_t)bh * kS + qrow1) * 2;
        g_ml[i0] = B20; g_ml[i0 + 1] = lr[0];
        g_ml[i1] = B21; g_ml[i1 + 1] = lr[1];
    }
}

// ---------------------------------------------------------------------------
// K3: attn_weights (unchanged from R12)
// ---------------------------------------------------------------------------
__global__ __launch_bounds__(256, 2) void k_attnw(const float* __restrict__ mask,
                                                  float* __restrict__ aw_out)
{
    extern __shared__ float sh[];
    float (*Qb)[128][68] = (float(*)[128][68])sh;
    float (*Kb)[64][68]  = (float(*)[64][68])(sh + 2 * 128 * 68);

    const int b = blockIdx.z;
    const int qbase = blockIdx.y * 128;
    const int kbase = blockIdx.x * 64;
    const int tid = threadIdx.x;
    const int wid = tid >> 5, lane = tid & 31;
    const int lg = lane >> 2, lt = lane & 3;
    const int mj = lane >> 3, mi2 = lane & 7;
    const int r0 = wid * 16;
    const int qrow0 = qbase + r0 + lg;
    const int qrow1 = qrow0 + 8;

    const float* qsrc = g_q + ((size_t)(b * kS + qbase)) * kE;
    const float* ksrc = g_k + ((size_t)(b * kS + kbase)) * kE;
    const int lrow = tid >> 4;
    const int ld4  = (tid & 15) << 2;

#pragma unroll
    for (int rr = 0; rr < 8; ++rr) {
        int q = lrow + rr * 16;
        cpa16(&Qb[0][q][ld4], qsrc + (size_t)q * kE + ld4);
    }
#pragma unroll
    for (int rr = 0; rr < 4; ++rr) {
        int kc = lrow + rr * 16;
        cpa16(&Kb[0][kc][ld4], ksrc + (size_t)kc * kE + ld4);
    }
    CPA_COMMIT();

    const uint32_t qa0 = sptr(&Qb[0][r0 + ((mj & 1) << 3) + mi2][(mj >> 1) << 2]);
    const uint32_t ka0 = sptr(&Kb[0][8 * (mj >> 1) + mi2][(mj & 1) << 2]);
    constexpr uint32_t QBUFB = 128 * 68 * 4;
    constexpr uint32_t KBUFB = 64 * 68 * 4;

    float mk2[8][4];
#pragma unroll
    for (int ni = 0; ni < 8; ++ni) {
        size_t col = (size_t)kbase + ni * 8 + lt * 2;
        float2 m0 = *(const float2*)(mask + (size_t)qrow0 * kS + col);
        float2 m1 = *(const float2*)(mask + (size_t)qrow1 * kS + col);
        mk2[ni][0] = m0.x * kL2E; mk2[ni][1] = m0.y * kL2E;
        mk2[ni][2] = m1.x * kL2E; mk2[ni][3] = m1.y * kL2E;
    }

    const float* mlp = g_ml + ((size_t)b * kH) * kS * 2;
    float2 mlA0 = *(const float2*)(mlp + (size_t)qrow0 * 2);
    float2 mlA1 = *(const float2*)(mlp + (size_t)qrow1 * 2);

    constexpr float kSL2E = kScale * kL2E;
    float aw[8][4] = {};

    for (int h = 0; h < kH; ++h) {
        const int cur = h & 1;
        CPA_WAIT(0);
        __syncthreads();
        if (h + 1 < kH) {
            const int nxt = cur ^ 1;
            const size_t hoff = (size_t)(h + 1) * kHD;
#pragma unroll
            for (int rr = 0; rr < 8; ++rr) {
                int q = lrow + rr * 16;
                cpa16(&Qb[nxt][q][ld4], qsrc + (size_t)q * kE + hoff + ld4);
            }
#pragma unroll
            for (int rr = 0; rr < 4; ++rr) {
                int kc = lrow + rr * 16;
                cpa16(&Kb[nxt][kc][ld4], ksrc + (size_t)kc * kE + hoff + ld4);
            }
            CPA_COMMIT();
        }

        float2 mlB0, mlB1;
        if (h + 1 < kH) {
            mlB0 = *(const float2*)(mlp + ((size_t)(h + 1) * kS + qrow0) * 2);
            mlB1 = *(const float2*)(mlp + ((size_t)(h + 1) * kS + qrow1) * 2);
        }

        float s[8][4] = {};
        const uint32_t qcur = qa0 + cur * QBUFB;
        const uint32_t kcur = ka0 + cur * KBUFB;
#pragma unroll
        for (int c = 0; c < 8; ++c) {
            uint32_t a[4];
            ldsm4(a, qcur + c * 32);
            const uint32_t kc4 = kcur + c * 32;
#pragma unroll
            for (int t = 0; t < 4; ++t) {
                uint32_t bb[4];
                ldsm4(bb, kc4 + t * (16 * 68 * 4));
                mma_tf32(s[2 * t],     a, bb);
                mma_tf32(s[2 * t + 1], a, bb + 2);
            }
        }

        float c20 = mlA0.x + __log2f(mlA0.y);
        float c21 = mlA1.x + __log2f(mlA1.y);
#pragma unroll
        for (int ni = 0; ni < 8; ++ni) {
            aw[ni][0] += ex2(fmaf(s[ni][0], kSL2E, mk2[ni][0]) - c20);
            aw[ni][1] += ex2(fmaf(s[ni][1], kSL2E, mk2[ni][1]) - c20);
            aw[ni][2] += ex2(fmaf(s[ni][2], kSL2E, mk2[ni][2]) - c21);
            aw[ni][3] += ex2(fmaf(s[ni][3], kSL2E, mk2[ni][3]) - c21);
        }
        mlA0 = mlB0;
        mlA1 = mlB1;
    }

#pragma unroll
    for (int ni = 0; ni < 8; ++ni) {
        int col = kbase + ni * 8 + lt * 2;
        float2 o0 = {aw[ni][0] * (1.0f / kH), aw[ni][1] * (1.0f / kH)};
        float2 o1 = {aw[ni][2] * (1.0f / kH), aw[ni][3] * (1.0f / kH)};
        *(float2*)(aw_out + (size_t)b * kS * kS + (size_t)qrow0 * kS + col) = o0;
        *(float2*)(aw_out + (size_t)b * kS * kS + (size_t)qrow1 * kS + col) = o1;
    }
}

// ---------------------------------------------------------------------------
// K4: output projection; A and B^T ldmatrix-fed, 2-stage cp.async.
// ---------------------------------------------------------------------------
__global__ __launch_bounds__(256) void k_oproj()
{
    extern __shared__ float sh[];
    const int m = blockIdx.z;
    const int cnt = g_cnt[m];
    const int rows = blockIdx.y * 128;
    if (rows >= cnt) return;

    const float* Wt = g_wo + (size_t)m * kE * kD;     // [d][e]
    const int* idx = g_idx + m * kNR;

    const int tid = threadIdx.x;
    const int wid = tid >> 5, lane = tid & 31;
    const int lg = lane >> 2, lt = lane & 3;
    const int mj = lane >> 3, mi2 = lane & 7;
    const int wm = wid & 3, wn = wid >> 2;
    const int cols = blockIdx.x * 128;

    float d[2][8][4] = {};

    const int arow = tid >> 3;
    const int ac4  = (tid & 7) << 2;
    const float* aptr[4];
    const float* bptr[4];
#pragma unroll
    for (int i = 0; i < 4; ++i) {
        aptr[i] = g_ctx + (size_t)idx[rows + arow + 32 * i] * kE + ac4;
        bptr[i] = Wt + (size_t)(cols + arow + 32 * i) * kE + ac4;
    }

    uint32_t aabase[2], bbbase[2];
#pragma unroll
    for (int st = 0; st < 2; ++st) {
        aabase[st] = sptr(sh + st * 4608 +
                          (wm * 32 + ((mj & 1) << 3) + mi2) * 36 + ((mj >> 1) << 2));
        bbbase[st] = sptr(sh + 9216 + st * 4608 +
                          (wn * 64 + 8 * (mj >> 1) + mi2) * 36 + ((mj & 1) << 2));
    }

    auto issue = [&](int st, int k0) {
        float* as = sh + st * 4608;
        float* bs = sh + 9216 + st * 4608;
#pragma unroll
        for (int i = 0; i < 4; ++i) {
            cpa16(as + (arow + 32 * i) * 36 + ac4, aptr[i] + k0);
            cpa16(bs + (arow + 32 * i) * 36 + ac4, bptr[i] + k0);
        }
    };

    issue(0, 0);
    CPA_COMMIT();

    constexpr int NIT = kE / 32;
    for (int kb = 0; kb < NIT; ++kb) {
        const int cur = kb & 1;
        CPA_WAIT(0);
        __syncthreads();
        if (kb + 1 < NIT) { issue(cur ^ 1, (kb + 1) * 32); CPA_COMMIT(); }

#pragma unroll
        for (int ks = 0; ks < 32; ks += 8) {
            uint32_t a[2][4];
            ldsm4(a[0], aabase[cur] + ks * 4);
            ldsm4(a[1], aabase[cur] + 2304 + ks * 4);
#pragma unroll
            for (int t = 0; t < 4; ++t) {
                uint32_t bb[4];
                ldsm4(bb, bbbase[cur] + t * 2304 + ks * 4);
                mma_tf32(d[0][2 * t],     a[0], bb);
                mma_tf32(d[0][2 * t + 1], a[0], bb + 2);
                mma_tf32(d[1][2 * t],     a[1], bb);
                mma_tf32(d[1][2 * t + 1], a[1], bb + 2);
            }
        }
    }

#pragma unroll
    for (int mi = 0; mi < 2; ++mi) {
#pragma unroll
        for (int hh = 0; hh < 2; ++hh) {
            int iloc = rows + wm * 32 + mi * 16 + hh * 8 + lg;
            if (iloc < cnt) {
                int row = idx[iloc];
                int c0 = hh * 2, c1 = hh * 2 + 1;
#pragma unroll
                for (int ni = 0; ni < 8; ++ni) {
                    int cl = ni * 8 + lt * 2;
                    float2 o = {d[mi][ni][c0], d[mi][ni][c1]};
                    *(float2*)(g_o + (size_t)row * kD + cols + wn * 64 + cl) = o;
                }
            }
        }
    }
}

// ---------------------------------------------------------------------------
// K5: final full-row RMSNorm (fp32)
// ---------------------------------------------------------------------------
__global__ __launch_bounds__(256) void k_rmsout(const int* __restrict__ mod_ids,
                                                const float* __restrict__ anw,
                                                float* __restrict__ out)
{
    const int rg = blockIdx.x;
    const int tid = threadIdx.x;
    const int mid = mod_ids[rg];
    const float* src = g_o + (size_t)rg * kD;

    float4 v = *(const float4*)(src + tid * 4);
    float ss = v.x * v.x + v.y * v.y + v.z * v.z + v.w * v.w;
#pragma unroll
    for (int off = 16; off > 0; off >>= 1)
        ss += __shfl_xor_sync(0xffffffffu, ss, off);

    __shared__ float red[8];
    __shared__ float scale_sh;
    if ((tid & 31) == 0) red[tid >> 5] = ss;
    __syncthreads();
    if (tid == 0) {
        float t = 0.0f;
#pragma unroll
        for (int w = 0; w < 8; ++w) t += red[w];
        scale_sh = rsqrtf(t * (1.0f / kD) + kEps);
    }
    __syncthreads();
    float sc = scale_sh;

    const float* w = anw + (size_t)mid * kD;
    float4 w4 = *(const float4*)(w + tid * 4);
    float4 o = {v.x * sc * w4.x, v.y * sc * w4.y, v.z * sc * w4.z, v.w * sc * w4.w};
    *(float4*)(out + (size_t)rg * kD + tid * 4) = o;
}

// ---------------------------------------------------------------------------
extern "C" void kernel_launch(void* const* d_in, const int* in_sizes, int n_in,
                              void* d_out, int out_size)
{
    const float* x         = (const float*)d_in[0];
    const float* attn_mask = (const float*)d_in[1];
    const int*   mod_ids   = (const int*)d_in[2];
    const float* Wq        = (const float*)d_in[3];
    const float* Wk        = (const float*)d_in[4];
    const float* Wv        = (const float*)d_in[5];
    const float* Wo        = (const float*)d_in[6];
    const float* qn_w      = (const float*)d_in[7];
    const float* kn_w      = (const float*)d_in[8];
    const float* anw       = (const float*)d_in[9];

    float* out = (float*)d_out;
    float* aw  = out + (size_t)kNR * kD;

    constexpr int kGemmSmem  = 18432 * 4;                              // 73728
    constexpr int kFlashSmem = (128 * 68 + 2 * 64 * 68 + 2 * 64 * 72) * 4;  // 106496
    constexpr int kAttnwSmem = 384 * 68 * 4;                           // 104448
    cudaFuncSetAttribute(k_qkv,   cudaFuncAttributeMaxDynamicSharedMemorySize, kGemmSmem);
    cudaFuncSetAttribute(k_oproj, cudaFuncAttributeMaxDynamicSharedMemorySize, kGemmSmem);
    cudaFuncSetAttribute(k_flash, cudaFuncAttributeMaxDynamicSharedMemorySize, kFlashSmem);
    cudaFuncSetAttribute(k_attnw, cudaFuncAttributeMaxDynamicSharedMemorySize, kAttnwSmem);

    dim3 blk(256);
    k_round_x<<<kNR * kD / 4 / 256, blk>>>(x);
    k_wtrans<<<dim3(32, 32, 8), blk>>>(Wq, Wk, Wv, Wo);
    k_mrow<<<kS, blk>>>(attn_mask);
    k_compact<<<1, 1024>>>(mod_ids);
    k_qkv  <<<dim3(kE / 128, kNR / 128, 6), blk, kGemmSmem>>>(qn_w, kn_w);
    k_flash<<<dim3(kS / 128, kB * kH), blk, kFlashSmem>>>(attn_mask);
    k_attnw<<<dim3(kS / 64, kS / 128, kB), blk, kAttnwSmem>>>(attn_mask, aw);
    k_oproj<<<dim3(kD / 128, kNR / 128, kM), blk, kGemmSmem>>>();
    k_rmsout<<<kNR, blk>>>(mod_ids, anw, out);
}

// round 15
// speedup vs baseline: 1.6561x; 1.0669x over previous
#include <cuda_runtime.h>
#include <cuda_fp16.h>
#include <cstdint>

// ---------------------------------------------------------------------------
// SimpleModalityUntiedAttention: B=2 S=2048 D=1024 H=16 HD=64 M=2 E=1024
// Round 15: k_attnw ELIMINATED. Static-bound softmax makes p final at
// compute time, so k_flash streams P to gmem as fp16 ([b][q][h][k]) and a
// memory-bound k_awred reduces over heads: aw = (1/16) sum_h p_h * il_h.
// GEMMs identical to R14 (transposed-weight ldmatrix feeds).
// ---------------------------------------------------------------------------

namespace {
constexpr int kB  = 2;
constexpr int kS  = 2048;
constexpr int kD  = 1024;
constexpr int kH  = 16;
constexpr int kHD = 64;
constexpr int kM  = 2;
constexpr int kE  = 1024;
constexpr int kNR = kB * kS;
constexpr float kEps   = 1e-5f;
constexpr float kScale = 0.125f;
constexpr float kL2E   = 1.44269504088896340736f;
}

__device__ float g_q[kNR * kE];
__device__ float g_k[kNR * kE];
__device__ float g_v[kNR * kE];
__device__ float g_ctx[kNR * kE];
__device__ float g_o[kNR * kD];
__device__ float g_ml[kB * kH * kS * 2];   // (B2 log2 units, sumexp)
__device__ float g_mrow2[kS];
__device__ int   g_idx[kM * kNR];
__device__ int   g_cnt[kM];
__device__ float g_xr[kNR * kD];
// TRANSPOSED tf32-rounded weights: [m][n][k]
__device__ float g_wq[kM * kD * kE];
__device__ float g_wk[kM * kD * kE];
__device__ float g_wv[kM * kD * kE];
__device__ float g_wo[kM * kE * kD];
// unnormalized probabilities, fp16, layout [b][q][h][k]  (268 MB)
__device__ __half g_p[(size_t)kB * kS * kH * kS];

__device__ __forceinline__ float f2tf(float x) {
    uint32_t u;
    asm("cvt.rna.tf32.f32 %0, %1;" : "=r"(u) : "f"(x));
    return __uint_as_float(u);
}
__device__ __forceinline__ uint32_t fu(float x) { return __float_as_uint(x); }
__device__ __forceinline__ float ex2(float x) {
    float r;
    asm("ex2.approx.f32 %0, %1;" : "=f"(r) : "f"(x));
    return r;
}

__device__ __forceinline__ void mma_tf32(float* d, const uint32_t* a, const uint32_t* b) {
    asm volatile(
        "mma.sync.aligned.m16n8k8.row.col.f32.tf32.tf32.f32 "
        "{%0,%1,%2,%3}, {%4,%5,%6,%7}, {%8,%9}, {%0,%1,%2,%3};"
        : "+f"(d[0]), "+f"(d[1]), "+f"(d[2]), "+f"(d[3])
        : "r"(a[0]), "r"(a[1]), "r"(a[2]), "r"(a[3]), "r"(b[0]), "r"(b[1]));
}

__device__ __forceinline__ void ldsm4(uint32_t* r, uint32_t saddr) {
    asm volatile("ldmatrix.sync.aligned.m8n8.x4.shared.b16 {%0,%1,%2,%3}, [%4];"
        : "=r"(r[0]), "=r"(r[1]), "=r"(r[2]), "=r"(r[3]) : "r"(saddr));
}
__device__ __forceinline__ uint32_t sptr(const void* p) {
    return (uint32_t)__cvta_generic_to_shared(p);
}

__device__ __forceinline__ void cpa16(void* dst_smem, const void* src) {
    uint32_t d = (uint32_t)__cvta_generic_to_shared(dst_smem);
    asm volatile("cp.async.cg.shared.global [%0], [%1], 16;" :: "r"(d), "l"(src));
}
#define CPA_COMMIT() asm volatile("cp.async.commit_group;")
#define CPA_WAIT(N)  asm volatile("cp.async.wait_group %0;" :: "n"(N))

// ---------------------------------------------------------------------------
// K-1a: tf32 round-copy of x
// ---------------------------------------------------------------------------
__global__ __launch_bounds__(256) void k_round_x(const float* __restrict__ x)
{
    int i = blockIdx.x * 256 + threadIdx.x;
    float4 v = ((const float4*)x)[i];
    float4 r = {f2tf(v.x), f2tf(v.y), f2tf(v.z), f2tf(v.w)};
    ((float4*)g_xr)[i] = r;
}

// ---------------------------------------------------------------------------
// K-1b: transpose + tf32-round all 8 weight matrices
// ---------------------------------------------------------------------------
__global__ __launch_bounds__(256) void k_wtrans(
    const float* __restrict__ Wq, const float* __restrict__ Wk,
    const float* __restrict__ Wv, const float* __restrict__ Wo)
{
    __shared__ float t[32][33];
    const int z = blockIdx.z;
    const int tsr = z >> 1, m = z & 1;
    const float* src = ((tsr == 0) ? Wq : (tsr == 1) ? Wk : (tsr == 2) ? Wv : Wo)
                       + (size_t)m * kD * kE;
    float* dst = ((tsr == 0) ? g_wq : (tsr == 1) ? g_wk : (tsr == 2) ? g_wv : g_wo)
                 + (size_t)m * kD * kE;
    const int k0 = blockIdx.y * 32, n0 = blockIdx.x * 32;
    const int tx = threadIdx.x & 31, ty = threadIdx.x >> 5;
#pragma unroll
    for (int r = 0; r < 4; ++r)
        t[ty + r * 8][tx] = f2tf(src[(size_t)(k0 + ty + r * 8) * 1024 + n0 + tx]);
    __syncthreads();
#pragma unroll
    for (int r = 0; r < 4; ++r)
        dst[(size_t)(n0 + ty + r * 8) * 1024 + k0 + tx] = t[tx][ty + r * 8];
}

// ---------------------------------------------------------------------------
// K-2: per-row mask max -> static softmax bound B2(q)
// ---------------------------------------------------------------------------
__global__ __launch_bounds__(256) void k_mrow(const float* __restrict__ mask)
{
    const int q = blockIdx.x;
    const int tid = threadIdx.x;
    float m = -3e38f;
    const float* row = mask + (size_t)q * kS;
    for (int k = tid; k < kS; k += 256) m = fmaxf(m, row[k]);
#pragma unroll
    for (int off = 16; off > 0; off >>= 1)
        m = fmaxf(m, __shfl_xor_sync(0xffffffffu, m, off));
    __shared__ float red[8];
    if ((tid & 31) == 0) red[tid >> 5] = m;
    __syncthreads();
    if (tid == 0) {
        float t = red[0];
#pragma unroll
        for (int w = 1; w < 8; ++w) t = fmaxf(t, red[w]);
        g_mrow2[q] = (8.25f + t) * kL2E;
    }
}

// ---------------------------------------------------------------------------
// K0: modality compaction
// ---------------------------------------------------------------------------
__global__ __launch_bounds__(1024) void k_compact(const int* __restrict__ mod_ids)
{
    __shared__ int cnt[kM];
    const int tid = threadIdx.x;
    if (tid < kM) cnt[tid] = 0;
    __syncthreads();
    for (int r = tid; r < kNR; r += 1024) {
        int m = mod_ids[r];
        int pos = atomicAdd(&cnt[m], 1);
        g_idx[m * kNR + pos] = r;
    }
    __syncthreads();
    int c0 = cnt[0], c1 = cnt[1];
    if (tid == 0) { g_cnt[0] = c0; g_cnt[1] = c1; }
    for (int i = c0 + tid; i < kNR; i += 1024) g_idx[i] = 0;
    for (int i = c1 + tid; i < kNR; i += 1024) g_idx[kNR + i] = 0;
}

// ---------------------------------------------------------------------------
// K1: QKV projection; A and B^T ldmatrix-fed, 2-stage cp.async.
// ---------------------------------------------------------------------------
__global__ __launch_bounds__(256) void k_qkv(
    const float* __restrict__ qn_w, const float* __restrict__ kn_w)
{
    extern __shared__ float sh[];
    const int z = blockIdx.z;
    const int m = z / 3;
    const int which = z % 3;
    const int cnt = g_cnt[m];
    const int rows = blockIdx.y * 128;
    if (rows >= cnt) return;

    const float* Wt = ((which == 0) ? g_wq : (which == 1) ? g_wk : g_wv)
                      + (size_t)m * kD * kE;
    float* Cout = (which == 0) ? g_q : (which == 1) ? g_k : g_v;
    const int* idx = g_idx + m * kNR;

    const int tid = threadIdx.x;
    const int wid = tid >> 5, lane = tid & 31;
    const int lg = lane >> 2, lt = lane & 3;
    const int mj = lane >> 3, mi2 = lane & 7;
    const int wm = wid & 3, wn = wid >> 2;
    const int cols = blockIdx.x * 128;

    float d[2][8][4] = {};

    const int arow = tid >> 3;
    const int ac4  = (tid & 7) << 2;
    const float* aptr[4];
    const float* bptr[4];
#pragma unroll
    for (int i = 0; i < 4; ++i) {
        aptr[i] = g_xr + (size_t)idx[rows + arow + 32 * i] * kD + ac4;
        bptr[i] = Wt + (size_t)(cols + arow + 32 * i) * kE + ac4;
    }

    uint32_t aabase[2], bbbase[2];
#pragma unroll
    for (int st = 0; st < 2; ++st) {
        aabase[st] = sptr(sh + st * 4608 +
                          (wm * 32 + ((mj & 1) << 3) + mi2) * 36 + ((mj >> 1) << 2));
        bbbase[st] = sptr(sh + 9216 + st * 4608 +
                          (wn * 64 + 8 * (mj >> 1) + mi2) * 36 + ((mj & 1) << 2));
    }

    auto issue = [&](int st, int k0) {
        float* as = sh + st * 4608;
        float* bs = sh + 9216 + st * 4608;
#pragma unroll
        for (int i = 0; i < 4; ++i) {
            cpa16(as + (arow + 32 * i) * 36 + ac4, aptr[i] + k0);
            cpa16(bs + (arow + 32 * i) * 36 + ac4, bptr[i] + k0);
        }
    };

    issue(0, 0);
    CPA_COMMIT();

    constexpr int NIT = kD / 32;
    for (int kb = 0; kb < NIT; ++kb) {
        const int cur = kb & 1;
        CPA_WAIT(0);
        __syncthreads();
        if (kb + 1 < NIT) { issue(cur ^ 1, (kb + 1) * 32); CPA_COMMIT(); }

#pragma unroll
        for (int ks = 0; ks < 32; ks += 8) {
            uint32_t a[2][4];
            ldsm4(a[0], aabase[cur] + ks * 4);
            ldsm4(a[1], aabase[cur] + 2304 + ks * 4);
#pragma unroll
            for (int t = 0; t < 4; ++t) {
                uint32_t bb[4];
                ldsm4(bb, bbbase[cur] + t * 2304 + ks * 4);
                mma_tf32(d[0][2 * t],     a[0], bb);
                mma_tf32(d[0][2 * t + 1], a[0], bb + 2);
                mma_tf32(d[1][2 * t],     a[1], bb);
                mma_tf32(d[1][2 * t + 1], a[1], bb + 2);
            }
        }
    }

    const float* wn_ptr = ((which == 0) ? qn_w : kn_w) + m * kHD;
#pragma unroll
    for (int mi = 0; mi < 2; ++mi) {
#pragma unroll
        for (int hh = 0; hh < 2; ++hh) {
            int iloc = rows + wm * 32 + mi * 16 + hh * 8 + lg;
            bool sel = (iloc < cnt);
            int row = idx[iloc];
            int c0 = hh * 2, c1 = hh * 2 + 1;
            if (which < 2) {
                float ss = 0.0f;
#pragma unroll
                for (int ni = 0; ni < 8; ++ni)
                    ss += d[mi][ni][c0] * d[mi][ni][c0] + d[mi][ni][c1] * d[mi][ni][c1];
                ss += __shfl_xor_sync(0xffffffffu, ss, 1);
                ss += __shfl_xor_sync(0xffffffffu, ss, 2);
                float sc = rsqrtf(ss * (1.0f / 64.0f) + kEps);
                if (sel) {
#pragma unroll
                    for (int ni = 0; ni < 8; ++ni) {
                        int cl = ni * 8 + lt * 2;
                        float2 o = {f2tf(d[mi][ni][c0] * sc * wn_ptr[cl]),
                                    f2tf(d[mi][ni][c1] * sc * wn_ptr[cl + 1])};
                        *(float2*)(Cout + (size_t)row * kE + cols + wn * 64 + cl) = o;
                    }
                }
            } else if (sel) {
#pragma unroll
                for (int ni = 0; ni < 8; ++ni) {
                    int cl = ni * 8 + lt * 2;
                    float2 o = {f2tf(d[mi][ni][c0]), f2tf(d[mi][ni][c1])};
                    *(float2*)(Cout + (size_t)row * kE + cols + wn * 64 + cl) = o;
                }
            }
        }
    }
}

// ---------------------------------------------------------------------------
// K2: flash attention (static-bound softmax) + fp16 P streaming to g_p.
// ---------------------------------------------------------------------------
__global__ __launch_bounds__(256, 2) void k_flash(const float* __restrict__ mask)
{
    extern __shared__ float sh[];
    float (*PQ)[68] = (float(*)[68])sh;
    float (*Kb)[64][68] = (float(*)[64][68])(sh + 128 * 68);
    float (*Vb)[64][72] = (float(*)[64][72])(sh + 256 * 68);

    const int bh = blockIdx.y;
    const int b = bh >> 4, h = bh & 15;
    const int qbase = blockIdx.x * 128;
    const int tid = threadIdx.x;
    const int wid = tid >> 5, lane = tid & 31;
    const int lg = lane >> 2, lt = lane & 3;
    const int mj = lane >> 3, mi2 = lane & 7;
    const int r0 = wid * 16;

    const float* qsrc = g_q + ((size_t)(b * kS + qbase)) * kE + h * kHD;
    const float* ksrc = g_k + ((size_t)(b * kS)) * kE + h * kHD;
    const float* vsrc = g_v + ((size_t)(b * kS)) * kE + h * kHD;

    const int lrow = tid >> 4;
    const int ld4  = (tid & 15) << 2;

#pragma unroll
    for (int rr = 0; rr < 8; ++rr) {
        int q = lrow + rr * 16;
        cpa16(&PQ[q][ld4], qsrc + (size_t)q * kE + ld4);
    }
    CPA_COMMIT();
#pragma unroll
    for (int rr = 0; rr < 4; ++rr) {
        int kc = lrow + rr * 16;
        cpa16(&Kb[0][kc][ld4], ksrc + (size_t)kc * kE + ld4);
        cpa16(&Vb[0][kc][ld4], vsrc + (size_t)kc * kE + ld4);
    }
    CPA_COMMIT();
    CPA_WAIT(1);
    __syncthreads();

    const uint32_t pa0 = sptr(&PQ[r0 + ((mj & 1) << 3) + mi2][(mj >> 1) << 2]);
    const uint32_t ka0 = sptr(&Kb[0][8 * (mj >> 1) + mi2][(mj & 1) << 2]);
    constexpr uint32_t KBUFB = 64 * 68 * 4;

    uint32_t qf[8][4];
#pragma unroll
    for (int c = 0; c < 8; ++c) ldsm4(qf[c], pa0 + c * 32);

    float oacc[8][4] = {};
    float lr[2] = {0.0f, 0.0f};
    const int qrow0 = qbase + r0 + lg;
    const int qrow1 = qrow0 + 8;
    const float B20 = g_mrow2[qrow0];
    const float B21 = g_mrow2[qrow1];
    constexpr float kSL2E = kScale * kL2E;

    // fp16 P destinations: layout [b][q][h][k]
    __half* pd0 = g_p + (((size_t)(b * kS) + qrow0) * kH + h) * kS + lt * 2;
    __half* pd1 = g_p + (((size_t)(b * kS) + qrow1) * kH + h) * kS + lt * 2;

    for (int kbi = 0; kbi < kS / 64; ++kbi) {
        const int cur = kbi & 1;
        CPA_WAIT(0);
        __syncthreads();
        if (kbi + 1 < kS / 64) {
            const int nxt = cur ^ 1;
            const size_t koff = (size_t)(kbi + 1) * 64;
#pragma unroll
            for (int rr = 0; rr < 4; ++rr) {
                int kc = lrow + rr * 16;
                cpa16(&Kb[nxt][kc][ld4], ksrc + (koff + kc) * kE + ld4);
                cpa16(&Vb[nxt][kc][ld4], vsrc + (koff + kc) * kE + ld4);
            }
            CPA_COMMIT();
        }

        float s[8][4] = {};
        const uint32_t kcur = ka0 + cur * KBUFB;
#pragma unroll
        for (int c = 0; c < 8; ++c) {
            const uint32_t kc4 = kcur + c * 32;
#pragma unroll
            for (int t = 0; t < 4; ++t) {
                uint32_t bb[4];
                ldsm4(bb, kc4 + t * (16 * 68 * 4));
                mma_tf32(s[2 * t],     qf[c], bb);
                mma_tf32(s[2 * t + 1], qf[c], bb + 2);
            }
        }

        const int kb = kbi * 64;
#pragma unroll
        for (int ni = 0; ni < 8; ++ni) {
            size_t col = (size_t)kb + ni * 8 + lt * 2;
            float2 m0 = *(const float2*)(mask + (size_t)qrow0 * kS + col);
            float2 m1 = *(const float2*)(mask + (size_t)qrow1 * kS + col);
            s[ni][0] = ex2(fmaf(s[ni][0], kSL2E, fmaf(m0.x, kL2E, -B20)));
            s[ni][1] = ex2(fmaf(s[ni][1], kSL2E, fmaf(m0.y, kL2E, -B20)));
            s[ni][2] = ex2(fmaf(s[ni][2], kSL2E, fmaf(m1.x, kL2E, -B21)));
            s[ni][3] = ex2(fmaf(s[ni][3], kSL2E, fmaf(m1.y, kL2E, -B21)));
            lr[0] += s[ni][0] + s[ni][1];
            lr[1] += s[ni][2] + s[ni][3];
            // stream p (final values; static bound => no renormalization)
            *(__half2*)(pd0 + kb + ni * 8) = __floats2half2_rn(s[ni][0], s[ni][1]);
            *(__half2*)(pd1 + kb + ni * 8) = __floats2half2_rn(s[ni][2], s[ni][3]);
        }

#pragma unroll
        for (int ni = 0; ni < 8; ++ni) {
            int cl = ni * 8 + lt * 2;
            float2 p0 = {f2tf(s[ni][0]), f2tf(s[ni][1])};
            float2 p1 = {f2tf(s[ni][2]), f2tf(s[ni][3])};
            *(float2*)&PQ[r0 + lg][cl] = p0;
            *(float2*)&PQ[r0 + 8 + lg][cl] = p1;
        }
        __syncwarp();

#pragma unroll
        for (int c = 0; c < 8; ++c) {
            int ks = c * 8;
            uint32_t a[4];
            ldsm4(a, pa0 + c * 32);
#pragma unroll
            for (int ni = 0; ni < 8; ++ni) {
                uint32_t bfr[2];
                bfr[0] = fu(Vb[cur][ks + lt][ni * 8 + lg]);
                bfr[1] = fu(Vb[cur][ks + 4 + lt][ni * 8 + lg]);
                mma_tf32(oacc[ni], a, bfr);
            }
        }
    }

    lr[0] += __shfl_xor_sync(0xffffffffu, lr[0], 1);
    lr[0] += __shfl_xor_sync(0xffffffffu, lr[0], 2);
    lr[1] += __shfl_xor_sync(0xffffffffu, lr[1], 1);
    lr[1] += __shfl_xor_sync(0xffffffffu, lr[1], 2);

    float il0 = 1.0f / lr[0], il1 = 1.0f / lr[1];
#pragma unroll
    for (int ni = 0; ni < 8; ++ni) {
        int cl = ni * 8 + lt * 2;
        float2 o0 = {f2tf(oacc[ni][0] * il0), f2tf(oacc[ni][1] * il0)};
        float2 o1 = {f2tf(oacc[ni][2] * il1), f2tf(oacc[ni][3] * il1)};
        *(float2*)(g_ctx + (size_t)(b * kS + qrow0) * kE + h * kHD + cl) = o0;
        *(float2*)(g_ctx + (size_t)(b * kS + qrow1) * kE + h * kHD + cl) = o1;
    }
    if (lt == 0) {
        size_t i0 = ((size_t)bh * kS + qrow0) * 2;
        size_t i1 = ((size_t)bh * kS + qrow1) * 2;
        g_ml[i0] = B20; g_ml[i0 + 1] = lr[0];
        g_ml[i1] = B21; g_ml[i1 + 1] = lr[1];
    }
}

// ---------------------------------------------------------------------------
// K3: attn_weights reduction: aw[b,q,k] = (1/16) sum_h p[b][q][h][k] * il_h.
// One block per (b,q) row; fully coalesced streaming over g_p.
// ---------------------------------------------------------------------------
__global__ __launch_bounds__(256) void k_awred(float* __restrict__ aw_out)
{
    const int bq = blockIdx.x;
    const int b = bq >> 11, q = bq & (kS - 1);
    const int tid = threadIdx.x;

    __shared__ float il[kH];
    if (tid < kH)
        il[tid] = (1.0f / kH) /
                  g_ml[(((size_t)(b * kH + tid)) * kS + q) * 2 + 1];
    __syncthreads();

    const __half* base = g_p + ((size_t)(b * kS) + q) * kH * kS;
    const int k0 = tid * 8;
    float acc[8] = {};
#pragma unroll 4
    for (int h = 0; h < kH; ++h) {
        const __half2* src = (const __half2*)(base + (size_t)h * kS + k0);
        float s = il[h];
#pragma unroll
        for (int j = 0; j < 4; ++j) {
            float2 v = __half22float2(src[j]);
            acc[2 * j]     = fmaf(v.x, s, acc[2 * j]);
            acc[2 * j + 1] = fmaf(v.y, s, acc[2 * j + 1]);
        }
    }
    float4* dst = (float4*)(aw_out + (size_t)b * kS * kS + (size_t)q * kS + k0);
    dst[0] = {acc[0], acc[1], acc[2], acc[3]};
    dst[1] = {acc[4], acc[5], acc[6], acc[7]};
}

// ---------------------------------------------------------------------------
// K4: output projection; A and B^T ldmatrix-fed, 2-stage cp.async.
// ---------------------------------------------------------------------------
__global__ __launch_bounds__(256) void k_oproj()
{
    extern __shared__ float sh[];
    const int m = blockIdx.z;
    const int cnt = g_cnt[m];
    const int rows = blockIdx.y * 128;
    if (rows >= cnt) return;

    const float* Wt = g_wo + (size_t)m * kE * kD;
    const int* idx = g_idx + m * kNR;

    const int tid = threadIdx.x;
    const int wid = tid >> 5, lane = tid & 31;
    const int lg = lane >> 2, lt = lane & 3;
    const int mj = lane >> 3, mi2 = lane & 7;
    const int wm = wid & 3, wn = wid >> 2;
    const int cols = blockIdx.x * 128;

    float d[2][8][4] = {};

    const int arow = tid >> 3;
    const int ac4  = (tid & 7) << 2;
    const float* aptr[4];
    const float* bptr[4];
#pragma unroll
    for (int i = 0; i < 4; ++i) {
        aptr[i] = g_ctx + (size_t)idx[rows + arow + 32 * i] * kE + ac4;
        bptr[i] = Wt + (size_t)(cols + arow + 32 * i) * kE + ac4;
    }

    uint32_t aabase[2], bbbase[2];
#pragma unroll
    for (int st = 0; st < 2; ++st) {
        aabase[st] = sptr(sh + st * 4608 +
                          (wm * 32 + ((mj & 1) << 3) + mi2) * 36 + ((mj >> 1) << 2));
        bbbase[st] = sptr(sh + 9216 + st * 4608 +
                          (wn * 64 + 8 * (mj >> 1) + mi2) * 36 + ((mj & 1) << 2));
    }

    auto issue = [&](int st, int k0) {
        float* as = sh + st * 4608;
        float* bs = sh + 9216 + st * 4608;
#pragma unroll
        for (int i = 0; i < 4; ++i) {
            cpa16(as + (arow + 32 * i) * 36 + ac4, aptr[i] + k0);
            cpa16(bs + (arow + 32 * i) * 36 + ac4, bptr[i] + k0);
        }
    };

    issue(0, 0);
    CPA_COMMIT();

    constexpr int NIT = kE / 32;
    for (int kb = 0; kb < NIT; ++kb) {
        const int cur = kb & 1;
        CPA_WAIT(0);
        __syncthreads();
        if (kb + 1 < NIT) { issue(cur ^ 1, (kb + 1) * 32); CPA_COMMIT(); }

#pragma unroll
        for (int ks = 0; ks < 32; ks += 8) {
            uint32_t a[2][4];
            ldsm4(a[0], aabase[cur] + ks * 4);
            ldsm4(a[1], aabase[cur] + 2304 + ks * 4);
#pragma unroll
            for (int t = 0; t < 4; ++t) {
                uint32_t bb[4];
                ldsm4(bb, bbbase[cur] + t * 2304 + ks * 4);
                mma_tf32(d[0][2 * t],     a[0], bb);
                mma_tf32(d[0][2 * t + 1], a[0], bb + 2);
                mma_tf32(d[1][2 * t],     a[1], bb);
                mma_tf32(d[1][2 * t + 1], a[1], bb + 2);
            }
        }
    }

#pragma unroll
    for (int mi = 0; mi < 2; ++mi) {
#pragma unroll
        for (int hh = 0; hh < 2; ++hh) {
            int iloc = rows + wm * 32 + mi * 16 + hh * 8 + lg;
            if (iloc < cnt) {
                int row = idx[iloc];
                int c0 = hh * 2, c1 = hh * 2 + 1;
#pragma unroll
                for (int ni = 0; ni < 8; ++ni) {
                    int cl = ni * 8 + lt * 2;
                    float2 o = {d[mi][ni][c0], d[mi][ni][c1]};
                    *(float2*)(g_o + (size_t)row * kD + cols + wn * 64 + cl) = o;
                }
            }
        }
    }
}

// ---------------------------------------------------------------------------
// K5: final full-row RMSNorm (fp32)
// ---------------------------------------------------------------------------
__global__ __launch_bounds__(256) void k_rmsout(const int* __restrict__ mod_ids,
                                                const float* __restrict__ anw,
                                                float* __restrict__ out)
{
    const int rg = blockIdx.x;
    const int tid = threadIdx.x;
    const int mid = mod_ids[rg];
    const float* src = g_o + (size_t)rg * kD;

    float4 v = *(const float4*)(src + tid * 4);
    float ss = v.x * v.x + v.y * v.y + v.z * v.z + v.w * v.w;
#pragma unroll
    for (int off = 16; off > 0; off >>= 1)
        ss += __shfl_xor_sync(0xffffffffu, ss, off);

    __shared__ float red[8];
    __shared__ float scale_sh;
    if ((tid & 31) == 0) red[tid >> 5] = ss;
    __syncthreads();
    if (tid == 0) {
        float t = 0.0f;
#pragma unroll
        for (int w = 0; w < 8; ++w) t += red[w];
        scale_sh = rsqrtf(t * (1.0f / kD) + kEps);
    }
    __syncthreads();
    float sc = scale_sh;

    const float* w = anw + (size_t)mid * kD;
    float4 w4 = *(const float4*)(w + tid * 4);
    float4 o = {v.x * sc * w4.x, v.y * sc * w4.y, v.z * sc * w4.z, v.w * sc * w4.w};
    *(float4*)(out + (size_t)rg * kD + tid * 4) = o;
}

// ---------------------------------------------------------------------------
extern "C" void kernel_launch(void* const* d_in, const int* in_sizes, int n_in,
                              void* d_out, int out_size)
{
    const float* x         = (const float*)d_in[0];
    const float* attn_mask = (const float*)d_in[1];
    const int*   mod_ids   = (const int*)d_in[2];
    const float* Wq        = (const float*)d_in[3];
    const float* Wk        = (const float*)d_in[4];
    const float* Wv        = (const float*)d_in[5];
    const float* Wo        = (const float*)d_in[6];
    const float* qn_w      = (const float*)d_in[7];
    const float* kn_w      = (const float*)d_in[8];
    const float* anw       = (const float*)d_in[9];

    float* out = (float*)d_out;
    float* aw  = out + (size_t)kNR * kD;

    constexpr int kGemmSmem  = 18432 * 4;                              // 73728
    constexpr int kFlashSmem = (128 * 68 + 2 * 64 * 68 + 2 * 64 * 72) * 4;  // 106496
    cudaFuncSetAttribute(k_qkv,   cudaFuncAttributeMaxDynamicSharedMemorySize, kGemmSmem);
    cudaFuncSetAttribute(k_oproj, cudaFuncAttributeMaxDynamicSharedMemorySize, kGemmSmem);
    cudaFuncSetAttribute(k_flash, cudaFuncAttributeMaxDynamicSharedMemorySize, kFlashSmem);

    dim3 blk(256);
    k_round_x<<<kNR * kD / 4 / 256, blk>>>(x);
    k_wtrans<<<dim3(32, 32, 8), blk>>>(Wq, Wk, Wv, Wo);
    k_mrow<<<kS, blk>>>(attn_mask);
    k_compact<<<1, 1024>>>(mod_ids);
    k_qkv  <<<dim3(kE / 128, kNR / 128, 6), blk, kGemmSmem>>>(qn_w, kn_w);
    k_flash<<<dim3(kS / 128, kB * kH), blk, kFlashSmem>>>(attn_mask);
    k_awred<<<kB * kS, blk>>>(aw);
    k_oproj<<<dim3(kD / 128, kNR / 128, kM), blk, kGemmSmem>>>();
    k_rmsout<<<kNR, blk>>>(mod_ids, anw, out);
}

// round 16
// speedup vs baseline: 1.9870x; 1.1998x over previous
#include <cuda_runtime.h>
#include <cuda_fp16.h>
#include <cstdint>

// ---------------------------------------------------------------------------
// SimpleModalityUntiedAttention: B=2 S=2048 D=1024 H=16 HD=64 M=2 E=1024
// Round 16: flash attention moved to fp16 mma (m16n8k16) — same 10-bit
// mantissa as tf32, half the mma count, half the QKV smem traffic. q/k/v
// now produced as fp16 by k_qkv. GEMMs/awred/oproj unchanged from R15.
// ---------------------------------------------------------------------------

namespace {
constexpr int kB  = 2;
constexpr int kS  = 2048;
constexpr int kD  = 1024;
constexpr int kH  = 16;
constexpr int kHD = 64;
constexpr int kM  = 2;
constexpr int kE  = 1024;
constexpr int kNR = kB * kS;
constexpr float kEps   = 1e-5f;
constexpr float kScale = 0.125f;
constexpr float kL2E   = 1.44269504088896340736f;
}

__device__ __half g_qh[kNR * kE];   // fp16 q (flash-only consumer)
__device__ __half g_kh[kNR * kE];
__device__ __half g_vh[kNR * kE];
__device__ float g_ctx[kNR * kE];
__device__ float g_o[kNR * kD];
__device__ float g_ml[kB * kH * kS * 2];   // (B2 log2 units, sumexp)
__device__ float g_mrow2[kS];
__device__ int   g_idx[kM * kNR];
__device__ int   g_cnt[kM];
__device__ float g_xr[kNR * kD];
// TRANSPOSED tf32-rounded weights: [m][n][k]
__device__ float g_wq[kM * kD * kE];
__device__ float g_wk[kM * kD * kE];
__device__ float g_wv[kM * kD * kE];
__device__ float g_wo[kM * kE * kD];
// unnormalized probabilities, fp16, layout [b][q][h][k]
__device__ __half g_p[(size_t)kB * kS * kH * kS];

__device__ __forceinline__ float f2tf(float x) {
    uint32_t u;
    asm("cvt.rna.tf32.f32 %0, %1;" : "=r"(u) : "f"(x));
    return __uint_as_float(u);
}
__device__ __forceinline__ uint32_t fu(float x) { return __float_as_uint(x); }
__device__ __forceinline__ float ex2(float x) {
    float r;
    asm("ex2.approx.f32 %0, %1;" : "=f"(r) : "f"(x));
    return r;
}

__device__ __forceinline__ void mma_tf32(float* d, const uint32_t* a, const uint32_t* b) {
    asm volatile(
        "mma.sync.aligned.m16n8k8.row.col.f32.tf32.tf32.f32 "
        "{%0,%1,%2,%3}, {%4,%5,%6,%7}, {%8,%9}, {%0,%1,%2,%3};"
        : "+f"(d[0]), "+f"(d[1]), "+f"(d[2]), "+f"(d[3])
        : "r"(a[0]), "r"(a[1]), "r"(a[2]), "r"(a[3]), "r"(b[0]), "r"(b[1]));
}

__device__ __forceinline__ void mma_f16(float* d, const uint32_t* a, const uint32_t* b) {
    asm volatile(
        "mma.sync.aligned.m16n8k16.row.col.f32.f16.f16.f32 "
        "{%0,%1,%2,%3}, {%4,%5,%6,%7}, {%8,%9}, {%0,%1,%2,%3};"
        : "+f"(d[0]), "+f"(d[1]), "+f"(d[2]), "+f"(d[3])
        : "r"(a[0]), "r"(a[1]), "r"(a[2]), "r"(a[3]), "r"(b[0]), "r"(b[1]));
}

__device__ __forceinline__ void ldsm4(uint32_t* r, uint32_t saddr) {
    asm volatile("ldmatrix.sync.aligned.m8n8.x4.shared.b16 {%0,%1,%2,%3}, [%4];"
        : "=r"(r[0]), "=r"(r[1]), "=r"(r[2]), "=r"(r[3]) : "r"(saddr));
}
__device__ __forceinline__ void ldsm4t(uint32_t* r, uint32_t saddr) {
    asm volatile("ldmatrix.sync.aligned.m8n8.x4.trans.shared.b16 {%0,%1,%2,%3}, [%4];"
        : "=r"(r[0]), "=r"(r[1]), "=r"(r[2]), "=r"(r[3]) : "r"(saddr));
}
__device__ __forceinline__ uint32_t sptr(const void* p) {
    return (uint32_t)__cvta_generic_to_shared(p);
}

__device__ __forceinline__ void cpa16(void* dst_smem, const void* src) {
    uint32_t d = (uint32_t)__cvta_generic_to_shared(dst_smem);
    asm volatile("cp.async.cg.shared.global [%0], [%1], 16;" :: "r"(d), "l"(src));
}
#define CPA_COMMIT() asm volatile("cp.async.commit_group;")
#define CPA_WAIT(N)  asm volatile("cp.async.wait_group %0;" :: "n"(N))

// ---------------------------------------------------------------------------
// K-1a: tf32 round-copy of x
// ---------------------------------------------------------------------------
__global__ __launch_bounds__(256) void k_round_x(const float* __restrict__ x)
{
    int i = blockIdx.x * 256 + threadIdx.x;
    float4 v = ((const float4*)x)[i];
    float4 r = {f2tf(v.x), f2tf(v.y), f2tf(v.z), f2tf(v.w)};
    ((float4*)g_xr)[i] = r;
}

// ---------------------------------------------------------------------------
// K-1b: transpose + tf32-round all 8 weight matrices
// ---------------------------------------------------------------------------
__global__ __launch_bounds__(256) void k_wtrans(
    const float* __restrict__ Wq, const float* __restrict__ Wk,
    const float* __restrict__ Wv, const float* __restrict__ Wo)
{
    __shared__ float t[32][33];
    const int z = blockIdx.z;
    const int tsr = z >> 1, m = z & 1;
    const float* src = ((tsr == 0) ? Wq : (tsr == 1) ? Wk : (tsr == 2) ? Wv : Wo)
                       + (size_t)m * kD * kE;
    float* dst = ((tsr == 0) ? g_wq : (tsr == 1) ? g_wk : (tsr == 2) ? g_wv : g_wo)
                 + (size_t)m * kD * kE;
    const int k0 = blockIdx.y * 32, n0 = blockIdx.x * 32;
    const int tx = threadIdx.x & 31, ty = threadIdx.x >> 5;
#pragma unroll
    for (int r = 0; r < 4; ++r)
        t[ty + r * 8][tx] = f2tf(src[(size_t)(k0 + ty + r * 8) * 1024 + n0 + tx]);
    __syncthreads();
#pragma unroll
    for (int r = 0; r < 4; ++r)
        dst[(size_t)(n0 + ty + r * 8) * 1024 + k0 + tx] = t[tx][ty + r * 8];
}

// ---------------------------------------------------------------------------
// K-2: per-row mask max -> static softmax bound B2(q)
// ---------------------------------------------------------------------------
__global__ __launch_bounds__(256) void k_mrow(const float* __restrict__ mask)
{
    const int q = blockIdx.x;
    const int tid = threadIdx.x;
    float m = -3e38f;
    const float* row = mask + (size_t)q * kS;
    for (int k = tid; k < kS; k += 256) m = fmaxf(m, row[k]);
#pragma unroll
    for (int off = 16; off > 0; off >>= 1)
        m = fmaxf(m, __shfl_xor_sync(0xffffffffu, m, off));
    __shared__ float red[8];
    if ((tid & 31) == 0) red[tid >> 5] = m;
    __syncthreads();
    if (tid == 0) {
        float t = red[0];
#pragma unroll
        for (int w = 1; w < 8; ++w) t = fmaxf(t, red[w]);
        g_mrow2[q] = (8.25f + t) * kL2E;
    }
}

// ---------------------------------------------------------------------------
// K0: modality compaction
// ---------------------------------------------------------------------------
__global__ __launch_bounds__(1024) void k_compact(const int* __restrict__ mod_ids)
{
    __shared__ int cnt[kM];
    const int tid = threadIdx.x;
    if (tid < kM) cnt[tid] = 0;
    __syncthreads();
    for (int r = tid; r < kNR; r += 1024) {
        int m = mod_ids[r];
        int pos = atomicAdd(&cnt[m], 1);
        g_idx[m * kNR + pos] = r;
    }
    __syncthreads();
    int c0 = cnt[0], c1 = cnt[1];
    if (tid == 0) { g_cnt[0] = c0; g_cnt[1] = c1; }
    for (int i = c0 + tid; i < kNR; i += 1024) g_idx[i] = 0;
    for (int i = c1 + tid; i < kNR; i += 1024) g_idx[kNR + i] = 0;
}

// ---------------------------------------------------------------------------
// K1: QKV projection; tf32 core unchanged; epilogue emits fp16 q/k/v.
// ---------------------------------------------------------------------------
__global__ __launch_bounds__(256) void k_qkv(
    const float* __restrict__ qn_w, const float* __restrict__ kn_w)
{
    extern __shared__ float sh[];
    const int z = blockIdx.z;
    const int m = z / 3;
    const int which = z % 3;
    const int cnt = g_cnt[m];
    const int rows = blockIdx.y * 128;
    if (rows >= cnt) return;

    const float* Wt = ((which == 0) ? g_wq : (which == 1) ? g_wk : g_wv)
                      + (size_t)m * kD * kE;
    __half* Cout = (which == 0) ? g_qh : (which == 1) ? g_kh : g_vh;
    const int* idx = g_idx + m * kNR;

    const int tid = threadIdx.x;
    const int wid = tid >> 5, lane = tid & 31;
    const int lg = lane >> 2, lt = lane & 3;
    const int mj = lane >> 3, mi2 = lane & 7;
    const int wm = wid & 3, wn = wid >> 2;
    const int cols = blockIdx.x * 128;

    float d[2][8][4] = {};

    const int arow = tid >> 3;
    const int ac4  = (tid & 7) << 2;
    const float* aptr[4];
    const float* bptr[4];
#pragma unroll
    for (int i = 0; i < 4; ++i) {
        aptr[i] = g_xr + (size_t)idx[rows + arow + 32 * i] * kD + ac4;
        bptr[i] = Wt + (size_t)(cols + arow + 32 * i) * kE + ac4;
    }

    uint32_t aabase[2], bbbase[2];
#pragma unroll
    for (int st = 0; st < 2; ++st) {
        aabase[st] = sptr(sh + st * 4608 +
                          (wm * 32 + ((mj & 1) << 3) + mi2) * 36 + ((mj >> 1) << 2));
        bbbase[st] = sptr(sh + 9216 + st * 4608 +
                          (wn * 64 + 8 * (mj >> 1) + mi2) * 36 + ((mj & 1) << 2));
    }

    auto issue = [&](int st, int k0) {
        float* as = sh + st * 4608;
        float* bs = sh + 9216 + st * 4608;
#pragma unroll
        for (int i = 0; i < 4; ++i) {
            cpa16(as + (arow + 32 * i) * 36 + ac4, aptr[i] + k0);
            cpa16(bs + (arow + 32 * i) * 36 + ac4, bptr[i] + k0);
        }
    };

    issue(0, 0);
    CPA_COMMIT();

    constexpr int NIT = kD / 32;
    for (int kb = 0; kb < NIT; ++kb) {
        const int cur = kb & 1;
        CPA_WAIT(0);
        __syncthreads();
        if (kb + 1 < NIT) { issue(cur ^ 1, (kb + 1) * 32); CPA_COMMIT(); }

#pragma unroll
        for (int ks = 0; ks < 32; ks += 8) {
            uint32_t a[2][4];
            ldsm4(a[0], aabase[cur] + ks * 4);
            ldsm4(a[1], aabase[cur] + 2304 + ks * 4);
#pragma unroll
            for (int t = 0; t < 4; ++t) {
                uint32_t bb[4];
                ldsm4(bb, bbbase[cur] + t * 2304 + ks * 4);
                mma_tf32(d[0][2 * t],     a[0], bb);
                mma_tf32(d[0][2 * t + 1], a[0], bb + 2);
                mma_tf32(d[1][2 * t],     a[1], bb);
                mma_tf32(d[1][2 * t + 1], a[1], bb + 2);
            }
        }
    }

    const float* wn_ptr = ((which == 0) ? qn_w : kn_w) + m * kHD;
#pragma unroll
    for (int mi = 0; mi < 2; ++mi) {
#pragma unroll
        for (int hh = 0; hh < 2; ++hh) {
            int iloc = rows + wm * 32 + mi * 16 + hh * 8 + lg;
            bool sel = (iloc < cnt);
            int row = idx[iloc];
            int c0 = hh * 2, c1 = hh * 2 + 1;
            if (which < 2) {
                float ss = 0.0f;
#pragma unroll
                for (int ni = 0; ni < 8; ++ni)
                    ss += d[mi][ni][c0] * d[mi][ni][c0] + d[mi][ni][c1] * d[mi][ni][c1];
                ss += __shfl_xor_sync(0xffffffffu, ss, 1);
                ss += __shfl_xor_sync(0xffffffffu, ss, 2);
                float sc = rsqrtf(ss * (1.0f / 64.0f) + kEps);
                if (sel) {
#pragma unroll
                    for (int ni = 0; ni < 8; ++ni) {
                        int cl = ni * 8 + lt * 2;
                        __half2 o = __floats2half2_rn(d[mi][ni][c0] * sc * wn_ptr[cl],
                                                      d[mi][ni][c1] * sc * wn_ptr[cl + 1]);
                        *(__half2*)(Cout + (size_t)row * kE + cols + wn * 64 + cl) = o;
                    }
                }
            } else if (sel) {
#pragma unroll
                for (int ni = 0; ni < 8; ++ni) {
                    int cl = ni * 8 + lt * 2;
                    __half2 o = __floats2half2_rn(d[mi][ni][c0], d[mi][ni][c1]);
                    *(__half2*)(Cout + (size_t)row * kE + cols + wn * 64 + cl) = o;
                }
            }
        }
    }
}

// ---------------------------------------------------------------------------
// K2: flash attention, fp16 mma (m16n8k16). Static-bound softmax, P streamed
// to g_p fp16. smem (halves): PQ[128][72] | Kb[2][64][72] | Vb[2][64][72]
// = 27648 h = 55296 B.
// ---------------------------------------------------------------------------
__global__ __launch_bounds__(256, 2) void k_flash(const float* __restrict__ mask)
{
    extern __shared__ float sh[];
    __half* PQ = (__half*)sh;            // [128][72]: Q, then P (warp-private rows)
    __half* Kb = PQ + 128 * 72;          // [2][64][72]
    __half* Vb = Kb + 2 * 64 * 72;       // [2][64][72]

    const int bh = blockIdx.y;
    const int b = bh >> 4, h = bh & 15;
    const int qbase = blockIdx.x * 128;
    const int tid = threadIdx.x;
    const int wid = tid >> 5, lane = tid & 31;
    const int lg = lane >> 2, lt = lane & 3;
    const int r0 = wid * 16;

    const __half* qsrc = g_qh + ((size_t)(b * kS + qbase)) * kE + h * kHD;
    const __half* ksrc = g_kh + ((size_t)(b * kS)) * kE + h * kHD;
    const __half* vsrc = g_vh + ((size_t)(b * kS)) * kE + h * kHD;

    // Q tile: 128 rows x 64 halves (1 row / thread, 4x cpa16)
    {
        int qr = tid >> 1, qc = (tid & 1) * 32;
#pragma unroll
        for (int j = 0; j < 4; ++j)
            cpa16(PQ + qr * 72 + qc + j * 8, qsrc + (size_t)qr * kE + qc + j * 8);
    }
    CPA_COMMIT();
    const int kr = tid >> 2, kc = (tid & 3) * 16;
    cpa16(Kb + kr * 72 + kc,     ksrc + (size_t)kr * kE + kc);
    cpa16(Kb + kr * 72 + kc + 8, ksrc + (size_t)kr * kE + kc + 8);
    cpa16(Vb + kr * 72 + kc,     vsrc + (size_t)kr * kE + kc);
    cpa16(Vb + kr * 72 + kc + 8, vsrc + (size_t)kr * kE + kc + 8);
    CPA_COMMIT();
    CPA_WAIT(1);          // Q ready
    __syncthreads();

    // ldmatrix bases (byte offsets)
    const uint32_t qa = sptr(PQ + (r0 + (lane & 15)) * 72 + ((lane >> 4) << 3));
    const uint32_t kboff = ((lane & 7) + ((lane >> 4) << 3)) * 144 + ((lane >> 3) & 1) * 16;
    const uint32_t vboff = ((lane & 7) + (((lane >> 3) & 1) << 3)) * 144 + (lane >> 4) * 16;
    const uint32_t kbase0 = sptr(Kb);
    const uint32_t vbase0 = sptr(Vb);
    constexpr uint32_t KVBUF = 64 * 72 * 2;   // bytes per stage

    // hoist Q a-frags: 4 k16-chunks x 4 regs
    uint32_t qf[4][4];
#pragma unroll
    for (int c = 0; c < 4; ++c) ldsm4(qf[c], qa + c * 32);

    float oacc[8][4] = {};
    float lr2[2] = {0.0f, 0.0f};
    const int qrow0 = qbase + r0 + lg;
    const int qrow1 = qrow0 + 8;
    const float B20 = g_mrow2[qrow0];
    const float B21 = g_mrow2[qrow1];
    constexpr float kSL2E = kScale * kL2E;

    __half* pd0 = g_p + (((size_t)(b * kS) + qrow0) * kH + h) * kS + lt * 2;
    __half* pd1 = g_p + (((size_t)(b * kS) + qrow1) * kH + h) * kS + lt * 2;

    for (int kbi = 0; kbi < kS / 64; ++kbi) {
        const int cur = kbi & 1;
        CPA_WAIT(0);
        __syncthreads();
        if (kbi + 1 < kS / 64) {
            const int nxt = cur ^ 1;
            const size_t koff = (size_t)(kbi + 1) * 64;
            cpa16(Kb + nxt * 4608 + kr * 72 + kc,     ksrc + (koff + kr) * kE + kc);
            cpa16(Kb + nxt * 4608 + kr * 72 + kc + 8, ksrc + (koff + kr) * kE + kc + 8);
            cpa16(Vb + nxt * 4608 + kr * 72 + kc,     vsrc + (koff + kr) * kE + kc);
            cpa16(Vb + nxt * 4608 + kr * 72 + kc + 8, vsrc + (koff + kr) * kE + kc + 8);
            CPA_COMMIT();
        }

        // S = Q K^T (fp16 mma; b-frags non-trans ldmatrix, 2 ni per x4)
        float s[8][4] = {};
        const uint32_t kcur = kbase0 + cur * KVBUF + kboff;
#pragma unroll
        for (int c = 0; c < 4; ++c) {
#pragma unroll
            for (int p = 0; p < 4; ++p) {
                uint32_t bb[4];
                ldsm4(bb, kcur + p * (16 * 144) + c * 32);
                mma_f16(s[2 * p],     qf[c], bb);
                mma_f16(s[2 * p + 1], qf[c], bb + 2);
            }
        }

        const int kb = kbi * 64;
#pragma unroll
        for (int ni = 0; ni < 8; ++ni) {
            size_t col = (size_t)kb + ni * 8 + lt * 2;
            float2 m0 = *(const float2*)(mask + (size_t)qrow0 * kS + col);
            float2 m1 = *(const float2*)(mask + (size_t)qrow1 * kS + col);
            s[ni][0] = ex2(fmaf(s[ni][0], kSL2E, fmaf(m0.x, kL2E, -B20)));
            s[ni][1] = ex2(fmaf(s[ni][1], kSL2E, fmaf(m0.y, kL2E, -B20)));
            s[ni][2] = ex2(fmaf(s[ni][2], kSL2E, fmaf(m1.x, kL2E, -B21)));
            s[ni][3] = ex2(fmaf(s[ni][3], kSL2E, fmaf(m1.y, kL2E, -B21)));
            lr2[0] += s[ni][0] + s[ni][1];
            lr2[1] += s[ni][2] + s[ni][3];
            // one conversion reused for smem P operand AND gmem stream
            __half2 h0 = __floats2half2_rn(s[ni][0], s[ni][1]);
            __half2 h1 = __floats2half2_rn(s[ni][2], s[ni][3]);
            *(__half2*)(PQ + (r0 + lg) * 72 + ni * 8 + lt * 2) = h0;
            *(__half2*)(PQ + (r0 + 8 + lg) * 72 + ni * 8 + lt * 2) = h1;
            *(__half2*)(pd0 + kb + ni * 8) = h0;
            *(__half2*)(pd1 + kb + ni * 8) = h1;
        }
        __syncwarp();

        // O += P V (P a-frags same addressing as Q; V b-frags trans ldmatrix)
        const uint32_t vcur = vbase0 + cur * KVBUF + vboff;
#pragma unroll
        for (int c = 0; c < 4; ++c) {
            uint32_t a[4];
            ldsm4(a, qa + c * 32);
#pragma unroll
            for (int p = 0; p < 4; ++p) {
                uint32_t vv[4];
                ldsm4t(vv, vcur + c * (16 * 144) + p * 32);
                mma_f16(oacc[2 * p],     a, vv);
                mma_f16(oacc[2 * p + 1], a, vv + 2);
            }
        }
    }

    lr2[0] += __shfl_xor_sync(0xffffffffu, lr2[0], 1);
    lr2[0] += __shfl_xor_sync(0xffffffffu, lr2[0], 2);
    lr2[1] += __shfl_xor_sync(0xffffffffu, lr2[1], 1);
    lr2[1] += __shfl_xor_sync(0xffffffffu, lr2[1], 2);

    float il0 = 1.0f / lr2[0], il1 = 1.0f / lr2[1];
#pragma unroll
    for (int ni = 0; ni < 8; ++ni) {
        int cl = ni * 8 + lt * 2;
        float2 o0 = {f2tf(oacc[ni][0] * il0), f2tf(oacc[ni][1] * il0)};
        float2 o1 = {f2tf(oacc[ni][2] * il1), f2tf(oacc[ni][3] * il1)};
        *(float2*)(g_ctx + (size_t)(b * kS + qrow0) * kE + h * kHD + cl) = o0;
        *(float2*)(g_ctx + (size_t)(b * kS + qrow1) * kE + h * kHD + cl) = o1;
    }
    if (lt == 0) {
        size_t i0 = ((size_t)bh * kS + qrow0) * 2;
        size_t i1 = ((size_t)bh * kS + qrow1) * 2;
        g_ml[i0] = B20; g_ml[i0 + 1] = lr2[0];
        g_ml[i1] = B21; g_ml[i1 + 1] = lr2[1];
    }
}

// ---------------------------------------------------------------------------
// K3: attn_weights reduction over heads (memory-bound)
// ---------------------------------------------------------------------------
__global__ __launch_bounds__(256) void k_awred(float* __restrict__ aw_out)
{
    const int bq = blockIdx.x;
    const int b = bq >> 11, q = bq & (kS - 1);
    const int tid = threadIdx.x;

    __shared__ float il[kH];
    if (tid < kH)
        il[tid] = (1.0f / kH) /
                  g_ml[(((size_t)(b * kH + tid)) * kS + q) * 2 + 1];
    __syncthreads();

    const __half* base = g_p + ((size_t)(b * kS) + q) * kH * kS;
    const int k0 = tid * 8;
    float acc[8] = {};
#pragma unroll 4
    for (int h = 0; h < kH; ++h) {
        const __half2* src = (const __half2*)(base + (size_t)h * kS + k0);
        float s = il[h];
#pragma unroll
        for (int j = 0; j < 4; ++j) {
            float2 v = __half22float2(src[j]);
            acc[2 * j]     = fmaf(v.x, s, acc[2 * j]);
            acc[2 * j + 1] = fmaf(v.y, s, acc[2 * j + 1]);
        }
    }
    float4* dst = (float4*)(aw_out + (size_t)b * kS * kS + (size_t)q * kS + k0);
    dst[0] = {acc[0], acc[1], acc[2], acc[3]};
    dst[1] = {acc[4], acc[5], acc[6], acc[7]};
}

// ---------------------------------------------------------------------------
// K4: output projection (unchanged: tf32, transposed-weight ldmatrix feeds)
// ---------------------------------------------------------------------------
__global__ __launch_bounds__(256) void k_oproj()
{
    extern __shared__ float sh[];
    const int m = blockIdx.z;
    const int cnt = g_cnt[m];
    const int rows = blockIdx.y * 128;
    if (rows >= cnt) return;

    const float* Wt = g_wo + (size_t)m * kE * kD;
    const int* idx = g_idx + m * kNR;

    const int tid = threadIdx.x;
    const int wid = tid >> 5, lane = tid & 31;
    const int lg = lane >> 2, lt = lane & 3;
    const int mj = lane >> 3, mi2 = lane & 7;
    const int wm = wid & 3, wn = wid >> 2;
    const int cols = blockIdx.x * 128;

    float d[2][8][4] = {};

    const int arow = tid >> 3;
    const int ac4  = (tid & 7) << 2;
    const float* aptr[4];
    const float* bptr[4];
#pragma unroll
    for (int i = 0; i < 4; ++i) {
        aptr[i] = g_ctx + (size_t)idx[rows + arow + 32 * i] * kE + ac4;
        bptr[i] = Wt + (size_t)(cols + arow + 32 * i) * kE + ac4;
    }

    uint32_t aabase[2], bbbase[2];
#pragma unroll
    for (int st = 0; st < 2; ++st) {
        aabase[st] = sptr(sh + st * 4608 +
                          (wm * 32 + ((mj & 1) << 3) + mi2) * 36 + ((mj >> 1) << 2));
        bbbase[st] = sptr(sh + 9216 + st * 4608 +
                          (wn * 64 + 8 * (mj >> 1) + mi2) * 36 + ((mj & 1) << 2));
    }

    auto issue = [&](int st, int k0) {
        float* as = sh + st * 4608;
        float* bs = sh + 9216 + st * 4608;
#pragma unroll
        for (int i = 0; i < 4; ++i) {
            cpa16(as + (arow + 32 * i) * 36 + ac4, aptr[i] + k0);
            cpa16(bs + (arow + 32 * i) * 36 + ac4, bptr[i] + k0);
        }
    };

    issue(0, 0);
    CPA_COMMIT();

    constexpr int NIT = kE / 32;
    for (int kb = 0; kb < NIT; ++kb) {
        const int cur = kb & 1;
        CPA_WAIT(0);
        __syncthreads();
        if (kb + 1 < NIT) { issue(cur ^ 1, (kb + 1) * 32); CPA_COMMIT(); }

#pragma unroll
        for (int ks = 0; ks < 32; ks += 8) {
            uint32_t a[2][4];
            ldsm4(a[0], aabase[cur] + ks * 4);
            ldsm4(a[1], aabase[cur] + 2304 + ks * 4);
#pragma unroll
            for (int t = 0; t < 4; ++t) {
                uint32_t bb[4];
                ldsm4(bb, bbbase[cur] + t * 2304 + ks * 4);
                mma_tf32(d[0][2 * t],     a[0], bb);
                mma_tf32(d[0][2 * t + 1], a[0], bb + 2);
                mma_tf32(d[1][2 * t],     a[1], bb);
                mma_tf32(d[1][2 * t + 1], a[1], bb + 2);
            }
        }
    }

#pragma unroll
    for (int mi = 0; mi < 2; ++mi) {
#pragma unroll
        for (int hh = 0; hh < 2; ++hh) {
            int iloc = rows + wm * 32 + mi * 16 + hh * 8 + lg;
            if (iloc < cnt) {
                int row = idx[iloc];
                int c0 = hh * 2, c1 = hh * 2 + 1;
#pragma unroll
                for (int ni = 0; ni < 8; ++ni) {
                    int cl = ni * 8 + lt * 2;
                    float2 o = {d[mi][ni][c0], d[mi][ni][c1]};
                    *(float2*)(g_o + (size_t)row * kD + cols + wn * 64 + cl) = o;
                }
            }
        }
    }
}

// ---------------------------------------------------------------------------
// K5: final full-row RMSNorm (fp32)
// ---------------------------------------------------------------------------
__global__ __launch_bounds__(256) void k_rmsout(const int* __restrict__ mod_ids,
                                                const float* __restrict__ anw,
                                                float* __restrict__ out)
{
    const int rg = blockIdx.x;
    const int tid = threadIdx.x;
    const int mid = mod_ids[rg];
    const float* src = g_o + (size_t)rg * kD;

    float4 v = *(const float4*)(src + tid * 4);
    float ss = v.x * v.x + v.y * v.y + v.z * v.z + v.w * v.w;
#pragma unroll
    for (int off = 16; off > 0; off >>= 1)
        ss += __shfl_xor_sync(0xffffffffu, ss, off);

    __shared__ float red[8];
    __shared__ float scale_sh;
    if ((tid & 31) == 0) red[tid >> 5] = ss;
    __syncthreads();
    if (tid == 0) {
        float t = 0.0f;
#pragma unroll
        for (int w = 0; w < 8; ++w) t += red[w];
        scale_sh = rsqrtf(t * (1.0f / kD) + kEps);
    }
    __syncthreads();
    float sc = scale_sh;

    const float* w = anw + (size_t)mid * kD;
    float4 w4 = *(const float4*)(w + tid * 4);
    float4 o = {v.x * sc * w4.x, v.y * sc * w4.y, v.z * sc * w4.z, v.w * sc * w4.w};
    *(float4*)(out + (size_t)rg * kD + tid * 4) = o;
}

// ---------------------------------------------------------------------------
extern "C" void kernel_launch(void* const* d_in, const int* in_sizes, int n_in,
                              void* d_out, int out_size)
{
    const float* x         = (const float*)d_in[0];
    const float* attn_mask = (const float*)d_in[1];
    const int*   mod_ids   = (const int*)d_in[2];
    const float* Wq        = (const float*)d_in[3];
    const float* Wk        = (const float*)d_in[4];
    const float* Wv        = (const float*)d_in[5];
    const float* Wo        = (const float*)d_in[6];
    const float* qn_w      = (const float*)d_in[7];
    const float* kn_w      = (const float*)d_in[8];
    const float* anw       = (const float*)d_in[9];

    float* out = (float*)d_out;
    float* aw  = out + (size_t)kNR * kD;

    constexpr int kGemmSmem  = 18432 * 4;   // 73728
    constexpr int kFlashSmem = 27648 * 2;   // 55296 (fp16 tiles)
    cudaFuncSetAttribute(k_qkv,   cudaFuncAttributeMaxDynamicSharedMemorySize, kGemmSmem);
    cudaFuncSetAttribute(k_oproj, cudaFuncAttributeMaxDynamicSharedMemorySize, kGemmSmem);
    cudaFuncSetAttribute(k_flash, cudaFuncAttributeMaxDynamicSharedMemorySize, kFlashSmem);

    dim3 blk(256);
    k_round_x<<<kNR * kD / 4 / 256, blk>>>(x);
    k_wtrans<<<dim3(32, 32, 8), blk>>>(Wq, Wk, Wv, Wo);
    k_mrow<<<kS, blk>>>(attn_mask);
    k_compact<<<1, 1024>>>(mod_ids);
    k_qkv  <<<dim3(kE / 128, kNR / 128, 6), blk, kGemmSmem>>>(qn_w, kn_w);
    k_flash<<<dim3(kS / 128, kB * kH), blk, kFlashSmem>>>(attn_mask);
    k_awred<<<kB * kS, blk>>>(aw);
    k_oproj<<<dim3(kD / 128, kNR / 128, kM), blk, kGemmSmem>>>();
    k_rmsout<<<kNR, blk>>>(mod_ids, anw, out);
}

// round 17
// speedup vs baseline: 2.1725x; 1.0933x over previous
#include <cuda_runtime.h>
#include <cuda_fp16.h>
#include <cstdint>

// ---------------------------------------------------------------------------
// SimpleModalityUntiedAttention: B=2 S=2048 D=1024 H=16 HD=64 M=2 E=1024
// Round 17: GEMMs moved to fp16 mma (m16n8k16, kblock=64) — x/weights/ctx
// stored fp16 (same 10-bit mantissa as tf32). Inner loops reuse flash's
// proven ldmatrix patterns. Flash/awred unchanged from R16.
// ---------------------------------------------------------------------------

namespace {
constexpr int kB  = 2;
constexpr int kS  = 2048;
constexpr int kD  = 1024;
constexpr int kH  = 16;
constexpr int kHD = 64;
constexpr int kM  = 2;
constexpr int kE  = 1024;
constexpr int kNR = kB * kS;
constexpr float kEps   = 1e-5f;
constexpr float kScale = 0.125f;
constexpr float kL2E   = 1.44269504088896340736f;
}

__device__ __half g_qh[kNR * kE];
__device__ __half g_kh[kNR * kE];
__device__ __half g_vh[kNR * kE];
__device__ __half g_ctxh[kNR * kE];
__device__ float g_o[kNR * kD];
__device__ float g_ml[kB * kH * kS * 2];   // (B2 log2 units, sumexp)
__device__ float g_mrow2[kS];
__device__ int   g_idx[kM * kNR];
__device__ int   g_cnt[kM];
__device__ __half g_xh[kNR * kD];
// TRANSPOSED fp16 weights: [m][n][k]
__device__ __half g_wq[kM * kD * kE];
__device__ __half g_wk[kM * kD * kE];
__device__ __half g_wv[kM * kD * kE];
__device__ __half g_wo[kM * kE * kD];
// unnormalized probabilities, fp16, layout [b][q][h][k]
__device__ __half g_p[(size_t)kB * kS * kH * kS];

__device__ __forceinline__ uint32_t fu(float x) { return __float_as_uint(x); }
__device__ __forceinline__ float ex2(float x) {
    float r;
    asm("ex2.approx.f32 %0, %1;" : "=f"(r) : "f"(x));
    return r;
}

__device__ __forceinline__ void mma_f16(float* d, const uint32_t* a, const uint32_t* b) {
    asm volatile(
        "mma.sync.aligned.m16n8k16.row.col.f32.f16.f16.f32 "
        "{%0,%1,%2,%3}, {%4,%5,%6,%7}, {%8,%9}, {%0,%1,%2,%3};"
        : "+f"(d[0]), "+f"(d[1]), "+f"(d[2]), "+f"(d[3])
        : "r"(a[0]), "r"(a[1]), "r"(a[2]), "r"(a[3]), "r"(b[0]), "r"(b[1]));
}

__device__ __forceinline__ void ldsm4(uint32_t* r, uint32_t saddr) {
    asm volatile("ldmatrix.sync.aligned.m8n8.x4.shared.b16 {%0,%1,%2,%3}, [%4];"
        : "=r"(r[0]), "=r"(r[1]), "=r"(r[2]), "=r"(r[3]) : "r"(saddr));
}
__device__ __forceinline__ void ldsm4t(uint32_t* r, uint32_t saddr) {
    asm volatile("ldmatrix.sync.aligned.m8n8.x4.trans.shared.b16 {%0,%1,%2,%3}, [%4];"
        : "=r"(r[0]), "=r"(r[1]), "=r"(r[2]), "=r"(r[3]) : "r"(saddr));
}
__device__ __forceinline__ uint32_t sptr(const void* p) {
    return (uint32_t)__cvta_generic_to_shared(p);
}

__device__ __forceinline__ void cpa16(void* dst_smem, const void* src) {
    uint32_t d = (uint32_t)__cvta_generic_to_shared(dst_smem);
    asm volatile("cp.async.cg.shared.global [%0], [%1], 16;" :: "r"(d), "l"(src));
}
#define CPA_COMMIT() asm volatile("cp.async.commit_group;")
#define CPA_WAIT(N)  asm volatile("cp.async.wait_group %0;" :: "n"(N))

// ---------------------------------------------------------------------------
// K-1a: fp16 round-copy of x
// ---------------------------------------------------------------------------
__global__ __launch_bounds__(256) void k_round_x(const float* __restrict__ x)
{
    int i = blockIdx.x * 256 + threadIdx.x;
    float4 v = ((const float4*)x)[i];
    __half2 h0 = __floats2half2_rn(v.x, v.y);
    __half2 h1 = __floats2half2_rn(v.z, v.w);
    ((__half2*)g_xh)[2 * i]     = h0;
    ((__half2*)g_xh)[2 * i + 1] = h1;
}

// ---------------------------------------------------------------------------
// K-1b: transpose + fp16-round all 8 weight matrices (32x33 smem tiles)
// ---------------------------------------------------------------------------
__global__ __launch_bounds__(256) void k_wtrans(
    const float* __restrict__ Wq, const float* __restrict__ Wk,
    const float* __restrict__ Wv, const float* __restrict__ Wo)
{
    __shared__ float t[32][33];
    const int z = blockIdx.z;
    const int tsr = z >> 1, m = z & 1;
    const float* src = ((tsr == 0) ? Wq : (tsr == 1) ? Wk : (tsr == 2) ? Wv : Wo)
                       + (size_t)m * kD * kE;
    __half* dst = ((tsr == 0) ? g_wq : (tsr == 1) ? g_wk : (tsr == 2) ? g_wv : g_wo)
                  + (size_t)m * kD * kE;
    const int k0 = blockIdx.y * 32, n0 = blockIdx.x * 32;
    const int tx = threadIdx.x & 31, ty = threadIdx.x >> 5;
#pragma unroll
    for (int r = 0; r < 4; ++r)
        t[ty + r * 8][tx] = src[(size_t)(k0 + ty + r * 8) * 1024 + n0 + tx];
    __syncthreads();
#pragma unroll
    for (int r = 0; r < 4; ++r)
        dst[(size_t)(n0 + ty + r * 8) * 1024 + k0 + tx] =
            __float2half_rn(t[tx][ty + r * 8]);
}

// ---------------------------------------------------------------------------
// K-2: per-row mask max -> static softmax bound B2(q)
// ---------------------------------------------------------------------------
__global__ __launch_bounds__(256) void k_mrow(const float* __restrict__ mask)
{
    const int q = blockIdx.x;
    const int tid = threadIdx.x;
    float m = -3e38f;
    const float* row = mask + (size_t)q * kS;
    for (int k = tid; k < kS; k += 256) m = fmaxf(m, row[k]);
#pragma unroll
    for (int off = 16; off > 0; off >>= 1)
        m = fmaxf(m, __shfl_xor_sync(0xffffffffu, m, off));
    __shared__ float red[8];
    if ((tid & 31) == 0) red[tid >> 5] = m;
    __syncthreads();
    if (tid == 0) {
        float t = red[0];
#pragma unroll
        for (int w = 1; w < 8; ++w) t = fmaxf(t, red[w]);
        g_mrow2[q] = (8.25f + t) * kL2E;
    }
}

// ---------------------------------------------------------------------------
// K0: modality compaction
// ---------------------------------------------------------------------------
__global__ __launch_bounds__(1024) void k_compact(const int* __restrict__ mod_ids)
{
    __shared__ int cnt[kM];
    const int tid = threadIdx.x;
    if (tid < kM) cnt[tid] = 0;
    __syncthreads();
    for (int r = tid; r < kNR; r += 1024) {
        int m = mod_ids[r];
        int pos = atomicAdd(&cnt[m], 1);
        g_idx[m * kNR + pos] = r;
    }
    __syncthreads();
    int c0 = cnt[0], c1 = cnt[1];
    if (tid == 0) { g_cnt[0] = c0; g_cnt[1] = c1; }
    for (int i = c0 + tid; i < kNR; i += 1024) g_idx[i] = 0;
    for (int i = c1 + tid; i < kNR; i += 1024) g_idx[kNR + i] = 0;
}

// ---------------------------------------------------------------------------
// fp16 GEMM smem (halves): As[st][128][72] at st*9216, Bs[st][128][72] at
// 18432 + st*9216. Total 36864 h = 73728 B. kblock=64, 2-stage.
// ---------------------------------------------------------------------------

// ---------------------------------------------------------------------------
// K1: QKV projection, fp16 mma m16n8k16, kblock=64.
// ---------------------------------------------------------------------------
__global__ __launch_bounds__(256) void k_qkv(
    const float* __restrict__ qn_w, const float* __restrict__ kn_w)
{
    extern __shared__ float sh[];
    __half* As = (__half*)sh;
    __half* Bs = As + 2 * 9216;

    const int z = blockIdx.z;
    const int m = z / 3;
    const int which = z % 3;
    const int cnt = g_cnt[m];
    const int rows = blockIdx.y * 128;
    if (rows >= cnt) return;

    const __half* Wt = ((which == 0) ? g_wq : (which == 1) ? g_wk : g_wv)
                       + (size_t)m * kD * kE;
    __half* Cout = (which == 0) ? g_qh : (which == 1) ? g_kh : g_vh;
    const int* idx = g_idx + m * kNR;

    const int tid = threadIdx.x;
    const int wid = tid >> 5, lane = tid & 31;
    const int lg = lane >> 2, lt = lane & 3;
    const int wm = wid & 3, wn = wid >> 2;
    const int cols = blockIdx.x * 128;

    float d[2][8][4] = {};

    const int arow = tid >> 1;          // 0..127
    const int ac   = (tid & 1) * 32;    // 0 / 32 halves
    const __half* aptr = g_xh + (size_t)idx[rows + arow] * kD + ac;
    const __half* bptr = Wt + (size_t)(cols + arow) * kE + ac;

    const uint32_t kboff = ((lane & 7) + ((lane >> 4) << 3)) * 144 + ((lane >> 3) & 1) * 16;
    uint32_t aab[2], bbb[2];
#pragma unroll
    for (int st = 0; st < 2; ++st) {
        aab[st] = sptr(As + st * 9216 + (wm * 32 + (lane & 15)) * 72 + ((lane >> 4) << 3));
        bbb[st] = sptr(Bs + st * 9216 + wn * 64 * 72) + kboff;
    }

    auto issue = [&](int st, int k0) {
        __half* as = As + st * 9216;
        __half* bs = Bs + st * 9216;
#pragma unroll
        for (int j = 0; j < 4; ++j) {
            cpa16(as + arow * 72 + ac + j * 8, aptr + k0 + j * 8);
            cpa16(bs + arow * 72 + ac + j * 8, bptr + k0 + j * 8);
        }
    };

    issue(0, 0);
    CPA_COMMIT();

    constexpr int NIT = kD / 64;
    for (int kb = 0; kb < NIT; ++kb) {
        const int cur = kb & 1;
        CPA_WAIT(0);
        __syncthreads();
        if (kb + 1 < NIT) { issue(cur ^ 1, (kb + 1) * 64); CPA_COMMIT(); }

#pragma unroll
        for (int c = 0; c < 4; ++c) {
            uint32_t a[2][4];
            ldsm4(a[0], aab[cur] + c * 32);
            ldsm4(a[1], aab[cur] + 16 * 144 + c * 32);
#pragma unroll
            for (int p = 0; p < 4; ++p) {
                uint32_t bb[4];
                ldsm4(bb, bbb[cur] + p * (16 * 144) + c * 32);
                mma_f16(d[0][2 * p],     a[0], bb);
                mma_f16(d[0][2 * p + 1], a[0], bb + 2);
                mma_f16(d[1][2 * p],     a[1], bb);
                mma_f16(d[1][2 * p + 1], a[1], bb + 2);
            }
        }
    }

    const float* wn_ptr = ((which == 0) ? qn_w : kn_w) + m * kHD;
#pragma unroll
    for (int mi = 0; mi < 2; ++mi) {
#pragma unroll
        for (int hh = 0; hh < 2; ++hh) {
            int iloc = rows + wm * 32 + mi * 16 + hh * 8 + lg;
            bool sel = (iloc < cnt);
            int row = idx[iloc];
            int c0 = hh * 2, c1 = hh * 2 + 1;
            if (which < 2) {
                float ss = 0.0f;
#pragma unroll
                for (int ni = 0; ni < 8; ++ni)
                    ss += d[mi][ni][c0] * d[mi][ni][c0] + d[mi][ni][c1] * d[mi][ni][c1];
                ss += __shfl_xor_sync(0xffffffffu, ss, 1);
                ss += __shfl_xor_sync(0xffffffffu, ss, 2);
                float sc = rsqrtf(ss * (1.0f / 64.0f) + kEps);
                if (sel) {
#pragma unroll
                    for (int ni = 0; ni < 8; ++ni) {
                        int cl = ni * 8 + lt * 2;
                        __half2 o = __floats2half2_rn(d[mi][ni][c0] * sc * wn_ptr[cl],
                                                      d[mi][ni][c1] * sc * wn_ptr[cl + 1]);
                        *(__half2*)(Cout + (size_t)row * kE + cols + wn * 64 + cl) = o;
                    }
                }
            } else if (sel) {
#pragma unroll
                for (int ni = 0; ni < 8; ++ni) {
                    int cl = ni * 8 + lt * 2;
                    __half2 o = __floats2half2_rn(d[mi][ni][c0], d[mi][ni][c1]);
                    *(__half2*)(Cout + (size_t)row * kE + cols + wn * 64 + cl) = o;
                }
            }
        }
    }
}

// ---------------------------------------------------------------------------
// K2: flash attention, fp16 mma (unchanged from R16 except ctx -> fp16)
// ---------------------------------------------------------------------------
__global__ __launch_bounds__(256, 2) void k_flash(const float* __restrict__ mask)
{
    extern __shared__ float sh[];
    __half* PQ = (__half*)sh;            // [128][72]
    __half* Kb = PQ + 128 * 72;          // [2][64][72]
    __half* Vb = Kb + 2 * 64 * 72;       // [2][64][72]

    const int bh = blockIdx.y;
    const int b = bh >> 4, h = bh & 15;
    const int qbase = blockIdx.x * 128;
    const int tid = threadIdx.x;
    const int wid = tid >> 5, lane = tid & 31;
    const int lg = lane >> 2, lt = lane & 3;
    const int r0 = wid * 16;

    const __half* qsrc = g_qh + ((size_t)(b * kS + qbase)) * kE + h * kHD;
    const __half* ksrc = g_kh + ((size_t)(b * kS)) * kE + h * kHD;
    const __half* vsrc = g_vh + ((size_t)(b * kS)) * kE + h * kHD;

    {
        int qr = tid >> 1, qc = (tid & 1) * 32;
#pragma unroll
        for (int j = 0; j < 4; ++j)
            cpa16(PQ + qr * 72 + qc + j * 8, qsrc + (size_t)qr * kE + qc + j * 8);
    }
    CPA_COMMIT();
    const int kr = tid >> 2, kc = (tid & 3) * 16;
    cpa16(Kb + kr * 72 + kc,     ksrc + (size_t)kr * kE + kc);
    cpa16(Kb + kr * 72 + kc + 8, ksrc + (size_t)kr * kE + kc + 8);
    cpa16(Vb + kr * 72 + kc,     vsrc + (size_t)kr * kE + kc);
    cpa16(Vb + kr * 72 + kc + 8, vsrc + (size_t)kr * kE + kc + 8);
    CPA_COMMIT();
    CPA_WAIT(1);
    __syncthreads();

    const uint32_t qa = sptr(PQ + (r0 + (lane & 15)) * 72 + ((lane >> 4) << 3));
    const uint32_t kboff = ((lane & 7) + ((lane >> 4) << 3)) * 144 + ((lane >> 3) & 1) * 16;
    const uint32_t vboff = ((lane & 7) + (((lane >> 3) & 1) << 3)) * 144 + (lane >> 4) * 16;
    const uint32_t kbase0 = sptr(Kb);
    const uint32_t vbase0 = sptr(Vb);
    constexpr uint32_t KVBUF = 64 * 72 * 2;

    uint32_t qf[4][4];
#pragma unroll
    for (int c = 0; c < 4; ++c) ldsm4(qf[c], qa + c * 32);

    float oacc[8][4] = {};
    float lr2[2] = {0.0f, 0.0f};
    const int qrow0 = qbase + r0 + lg;
    const int qrow1 = qrow0 + 8;
    const float B20 = g_mrow2[qrow0];
    const float B21 = g_mrow2[qrow1];
    constexpr float kSL2E = kScale * kL2E;

    __half* pd0 = g_p + (((size_t)(b * kS) + qrow0) * kH + h) * kS + lt * 2;
    __half* pd1 = g_p + (((size_t)(b * kS) + qrow1) * kH + h) * kS + lt * 2;

    for (int kbi = 0; kbi < kS / 64; ++kbi) {
        const int cur = kbi & 1;
        CPA_WAIT(0);
        __syncthreads();
        if (kbi + 1 < kS / 64) {
            const int nxt = cur ^ 1;
            const size_t koff = (size_t)(kbi + 1) * 64;
            cpa16(Kb + nxt * 4608 + kr * 72 + kc,     ksrc + (koff + kr) * kE + kc);
            cpa16(Kb + nxt * 4608 + kr * 72 + kc + 8, ksrc + (koff + kr) * kE + kc + 8);
            cpa16(Vb + nxt * 4608 + kr * 72 + kc,     vsrc + (koff + kr) * kE + kc);
            cpa16(Vb + nxt * 4608 + kr * 72 + kc + 8, vsrc + (koff + kr) * kE + kc + 8);
            CPA_COMMIT();
        }

        float s[8][4] = {};
        const uint32_t kcur = kbase0 + cur * KVBUF + kboff;
#pragma unroll
        for (int c = 0; c < 4; ++c) {
#pragma unroll
            for (int p = 0; p < 4; ++p) {
                uint32_t bb[4];
                ldsm4(bb, kcur + p * (16 * 144) + c * 32);
                mma_f16(s[2 * p],     qf[c], bb);
                mma_f16(s[2 * p + 1], qf[c], bb + 2);
            }
        }

        const int kb = kbi * 64;
#pragma unroll
        for (int ni = 0; ni < 8; ++ni) {
            size_t col = (size_t)kb + ni * 8 + lt * 2;
            float2 m0 = *(const float2*)(mask + (size_t)qrow0 * kS + col);
            float2 m1 = *(const float2*)(mask + (size_t)qrow1 * kS + col);
            s[ni][0] = ex2(fmaf(s[ni][0], kSL2E, fmaf(m0.x, kL2E, -B20)));
            s[ni][1] = ex2(fmaf(s[ni][1], kSL2E, fmaf(m0.y, kL2E, -B20)));
            s[ni][2] = ex2(fmaf(s[ni][2], kSL2E, fmaf(m1.x, kL2E, -B21)));
            s[ni][3] = ex2(fmaf(s[ni][3], kSL2E, fmaf(m1.y, kL2E, -B21)));
            lr2[0] += s[ni][0] + s[ni][1];
            lr2[1] += s[ni][2] + s[ni][3];
            __half2 h0 = __floats2half2_rn(s[ni][0], s[ni][1]);
            __half2 h1 = __floats2half2_rn(s[ni][2], s[ni][3]);
            *(__half2*)(PQ + (r0 + lg) * 72 + ni * 8 + lt * 2) = h0;
            *(__half2*)(PQ + (r0 + 8 + lg) * 72 + ni * 8 + lt * 2) = h1;
            *(__half2*)(pd0 + kb + ni * 8) = h0;
            *(__half2*)(pd1 + kb + ni * 8) = h1;
        }
        __syncwarp();

        const uint32_t vcur = vbase0 + cur * KVBUF + vboff;
#pragma unroll
        for (int c = 0; c < 4; ++c) {
            uint32_t a[4];
            ldsm4(a, qa + c * 32);
#pragma unroll
            for (int p = 0; p < 4; ++p) {
                uint32_t vv[4];
                ldsm4t(vv, vcur + c * (16 * 144) + p * 32);
                mma_f16(oacc[2 * p],     a, vv);
                mma_f16(oacc[2 * p + 1], a, vv + 2);
            }
        }
    }

    lr2[0] += __shfl_xor_sync(0xffffffffu, lr2[0], 1);
    lr2[0] += __shfl_xor_sync(0xffffffffu, lr2[0], 2);
    lr2[1] += __shfl_xor_sync(0xffffffffu, lr2[1], 1);
    lr2[1] += __shfl_xor_sync(0xffffffffu, lr2[1], 2);

    float il0 = 1.0f / lr2[0], il1 = 1.0f / lr2[1];
#pragma unroll
    for (int ni = 0; ni < 8; ++ni) {
        int cl = ni * 8 + lt * 2;
        __half2 o0 = __floats2half2_rn(oacc[ni][0] * il0, oacc[ni][1] * il0);
        __half2 o1 = __floats2half2_rn(oacc[ni][2] * il1, oacc[ni][3] * il1);
        *(__half2*)(g_ctxh + (size_t)(b * kS + qrow0) * kE + h * kHD + cl) = o0;
        *(__half2*)(g_ctxh + (size_t)(b * kS + qrow1) * kE + h * kHD + cl) = o1;
    }
    if (lt == 0) {
        size_t i0 = ((size_t)bh * kS + qrow0) * 2;
        size_t i1 = ((size_t)bh * kS + qrow1) * 2;
        g_ml[i0] = B20; g_ml[i0 + 1] = lr2[0];
        g_ml[i1] = B21; g_ml[i1 + 1] = lr2[1];
    }
}

// ---------------------------------------------------------------------------
// K3: attn_weights reduction over heads (memory-bound)
// ---------------------------------------------------------------------------
__global__ __launch_bounds__(256) void k_awred(float* __restrict__ aw_out)
{
    const int bq = blockIdx.x;
    const int b = bq >> 11, q = bq & (kS - 1);
    const int tid = threadIdx.x;

    __shared__ float il[kH];
    if (tid < kH)
        il[tid] = (1.0f / kH) /
                  g_ml[(((size_t)(b * kH + tid)) * kS + q) * 2 + 1];
    __syncthreads();

    const __half* base = g_p + ((size_t)(b * kS) + q) * kH * kS;
    const int k0 = tid * 8;
    float acc[8] = {};
#pragma unroll 4
    for (int h = 0; h < kH; ++h) {
        const __half2* src = (const __half2*)(base + (size_t)h * kS + k0);
        float s = il[h];
#pragma unroll
        for (int j = 0; j < 4; ++j) {
            float2 v = __half22float2(src[j]);
            acc[2 * j]     = fmaf(v.x, s, acc[2 * j]);
            acc[2 * j + 1] = fmaf(v.y, s, acc[2 * j + 1]);
        }
    }
    float4* dst = (float4*)(aw_out + (size_t)b * kS * kS + (size_t)q * kS + k0);
    dst[0] = {acc[0], acc[1], acc[2], acc[3]};
    dst[1] = {acc[4], acc[5], acc[6], acc[7]};
}

// ---------------------------------------------------------------------------
// K4: output projection, fp16 mma m16n8k16, kblock=64.
// ---------------------------------------------------------------------------
__global__ __launch_bounds__(256) void k_oproj()
{
    extern __shared__ float sh[];
    __half* As = (__half*)sh;
    __half* Bs = As + 2 * 9216;

    const int m = blockIdx.z;
    const int cnt = g_cnt[m];
    const int rows = blockIdx.y * 128;
    if (rows >= cnt) return;

    const __half* Wt = g_wo + (size_t)m * kE * kD;
    const int* idx = g_idx + m * kNR;

    const int tid = threadIdx.x;
    const int wid = tid >> 5, lane = tid & 31;
    const int lg = lane >> 2, lt = lane & 3;
    const int wm = wid & 3, wn = wid >> 2;
    const int cols = blockIdx.x * 128;

    float d[2][8][4] = {};

    const int arow = tid >> 1;
    const int ac   = (tid & 1) * 32;
    const __half* aptr = g_ctxh + (size_t)idx[rows + arow] * kE + ac;
    const __half* bptr = Wt + (size_t)(cols + arow) * kE + ac;

    const uint32_t kboff = ((lane & 7) + ((lane >> 4) << 3)) * 144 + ((lane >> 3) & 1) * 16;
    uint32_t aab[2], bbb[2];
#pragma unroll
    for (int st = 0; st < 2; ++st) {
        aab[st] = sptr(As + st * 9216 + (wm * 32 + (lane & 15)) * 72 + ((lane >> 4) << 3));
        bbb[st] = sptr(Bs + st * 9216 + wn * 64 * 72) + kboff;
    }

    auto issue = [&](int st, int k0) {
        __half* as = As + st * 9216;
        __half* bs = Bs + st * 9216;
#pragma unroll
        for (int j = 0; j < 4; ++j) {
            cpa16(as + arow * 72 + ac + j * 8, aptr + k0 + j * 8);
            cpa16(bs + arow * 72 + ac + j * 8, bptr + k0 + j * 8);
        }
    };

    issue(0, 0);
    CPA_COMMIT();

    constexpr int NIT = kE / 64;
    for (int kb = 0; kb < NIT; ++kb) {
        const int cur = kb & 1;
        CPA_WAIT(0);
        __syncthreads();
        if (kb + 1 < NIT) { issue(cur ^ 1, (kb + 1) * 64); CPA_COMMIT(); }

#pragma unroll
        for (int c = 0; c < 4; ++c) {
            uint32_t a[2][4];
            ldsm4(a[0], aab[cur] + c * 32);
            ldsm4(a[1], aab[cur] + 16 * 144 + c * 32);
#pragma unroll
            for (int p = 0; p < 4; ++p) {
                uint32_t bb[4];
                ldsm4(bb, bbb[cur] + p * (16 * 144) + c * 32);
                mma_f16(d[0][2 * p],     a[0], bb);
                mma_f16(d[0][2 * p + 1], a[0], bb + 2);
                mma_f16(d[1][2 * p],     a[1], bb);
                mma_f16(d[1][2 * p + 1], a[1], bb + 2);
            }
        }
    }

#pragma unroll
    for (int mi = 0; mi < 2; ++mi) {
#pragma unroll
        for (int hh = 0; hh < 2; ++hh) {
            int iloc = rows + wm * 32 + mi * 16 + hh * 8 + lg;
            if (iloc < cnt) {
                int row = idx[iloc];
                int c0 = hh * 2, c1 = hh * 2 + 1;
#pragma unroll
                for (int ni = 0; ni < 8; ++ni) {
                    int cl = ni * 8 + lt * 2;
                    float2 o = {d[mi][ni][c0], d[mi][ni][c1]};
                    *(float2*)(g_o + (size_t)row * kD + cols + wn * 64 + cl) = o;
                }
            }
        }
    }
}

// ---------------------------------------------------------------------------
// K5: final full-row RMSNorm (fp32)
// ---------------------------------------------------------------------------
__global__ __launch_bounds__(256) void k_rmsout(const int* __restrict__ mod_ids,
                                                const float* __restrict__ anw,
                                                float* __restrict__ out)
{
    const int rg = blockIdx.x;
    const int tid = threadIdx.x;
    const int mid = mod_ids[rg];
    const float* src = g_o + (size_t)rg * kD;

    float4 v = *(const float4*)(src + tid * 4);
    float ss = v.x * v.x + v.y * v.y + v.z * v.z + v.w * v.w;
#pragma unroll
    for (int off = 16; off > 0; off >>= 1)
        ss += __shfl_xor_sync(0xffffffffu, ss, off);

    __shared__ float red[8];
    __shared__ float scale_sh;
    if ((tid & 31) == 0) red[tid >> 5] = ss;
    __syncthreads();
    if (tid == 0) {
        float t = 0.0f;
#pragma unroll
        for (int w = 0; w < 8; ++w) t += red[w];
        scale_sh = rsqrtf(t * (1.0f / kD) + kEps);
    }
    __syncthreads();
    float sc = scale_sh;

    const float* w = anw + (size_t)mid * kD;
    float4 w4 = *(const float4*)(w + tid * 4);
    float4 o = {v.x * sc * w4.x, v.y * sc * w4.y, v.z * sc * w4.z, v.w * sc * w4.w};
    *(float4*)(out + (size_t)rg * kD + tid * 4) = o;
}

// ---------------------------------------------------------------------------
extern "C" void kernel_launch(void* const* d_in, const int* in_sizes, int n_in,
                              void* d_out, int out_size)
{
    const float* x         = (const float*)d_in[0];
    const float* attn_mask = (const float*)d_in[1];
    const int*   mod_ids   = (const int*)d_in[2];
    const float* Wq        = (const float*)d_in[3];
    const float* Wk        = (const float*)d_in[4];
    const float* Wv        = (const float*)d_in[5];
    const float* Wo        = (const float*)d_in[6];
    const float* qn_w      = (const float*)d_in[7];
    const float* kn_w      = (const float*)d_in[8];
    const float* anw       = (const float*)d_in[9];

    float* out = (float*)d_out;
    float* aw  = out + (size_t)kNR * kD;

    constexpr int kGemmSmem  = 36864 * 2;   // 73728 B (fp16 tiles)
    constexpr int kFlashSmem = 27648 * 2;   // 55296 B
    cudaFuncSetAttribute(k_qkv,   cudaFuncAttributeMaxDynamicSharedMemorySize, kGemmSmem);
    cudaFuncSetAttribute(k_oproj, cudaFuncAttributeMaxDynamicSharedMemorySize, kGemmSmem);
    cudaFuncSetAttribute(k_flash, cudaFuncAttributeMaxDynamicSharedMemorySize, kFlashSmem);

    dim3 blk(256);
    k_round_x<<<kNR * kD / 4 / 256, blk>>>(x);
    k_wtrans<<<dim3(32, 32, 8), blk>>>(Wq, Wk, Wv, Wo);
    k_mrow<<<kS, blk>>>(attn_mask);
    k_compact<<<1, 1024>>>(mod_ids);
    k_qkv  <<<dim3(kE / 128, kNR / 128, 6), blk, kGemmSmem>>>(qn_w, kn_w);
    k_flash<<<dim3(kS / 128, kB * kH), blk, kFlashSmem>>>(attn_mask);
    k_awred<<<kB * kS, blk>>>(aw);
    k_oproj<<<dim3(kD / 128, kNR / 128, kM), blk, kGemmSmem>>>();
    k_rmsout<<<kNR, blk>>>(mod_ids, anw, out);
}